// round 3
// baseline (speedup 1.0000x reference)
#include <cuda_runtime.h>
#include <math.h>

// ---------------- problem constants (fixed shapes) ----------------
#define MAXN 50000
#define MAXE 800000
#define FIN  512
#define D1   256      // H1 * C1
#define H1   8
#define C1   32
#define OUTC 64

// ---------------- scratch (static device globals; no allocation) ----------------
__device__ float g_xw1[MAXN * D1];      // layer1 linear output  [N, 8, 32]
__device__ float g_h[MAXN * D1];        // layer1 output after elu
__device__ float g_h2[MAXN * OUTC];     // layer2 linear output
__device__ float g_as1[MAXN * H1];
__device__ float g_ad1[MAXN * H1];
__device__ float g_as2[MAXN];
__device__ float g_ad2[MAXN];
__device__ int   g_deg[MAXN];
__device__ int   g_off[MAXN + 1];
__device__ int   g_cur[MAXN];
__device__ int   g_csr[MAXE + MAXN];    // src node ids grouped by dst
__device__ int   g_is64;                // 1 if edge_index stored as int64, 0 if int32

// ---------------- edge dtype detection ----------------
// If edge buffer holds int64 node ids (< 2^32), every odd 32-bit word is 0.
// If it holds int32 ids, odd words are real node ids — all-zero is ~impossible.
__global__ void detect_k(const unsigned* __restrict__ ew) {
    int t = threadIdx.x;  // 64 threads
    unsigned w = ew[2 * t + 1];
    unsigned nz = __ballot_sync(0xffffffffu, w != 0u);
    __shared__ unsigned s[2];
    if ((t & 31) == 0) s[t >> 5] = nz;
    __syncthreads();
    if (t == 0) g_is64 = ((s[0] | s[1]) == 0u) ? 1 : 0;
}

__device__ __forceinline__ int edge_at(const void* ew, int idx) {
    if (g_is64) return (int)((const long long*)ew)[idx];
    return ((const int*)ew)[idx];
}

// ---------------- CSR construction ----------------
__global__ void zero_deg_k(int n) {
    int i = blockIdx.x * blockDim.x + threadIdx.x;
    if (i < n) g_deg[i] = 0;
}

__global__ void count_deg_k(const void* __restrict__ ew, int E, int N) {
    int e = blockIdx.x * blockDim.x + threadIdx.x;
    int ET = E + N;
    if (e >= ET) return;
    int dst = (e < E) ? edge_at(ew, E + e) : (e - E);
    if ((unsigned)dst < (unsigned)N) atomicAdd(&g_deg[dst], 1);
}

// single-block 2-level exclusive scan over g_deg -> g_off, g_cur
__global__ void scan_k(int n) {
    __shared__ int sums[1024];
    int tid = threadIdx.x;
    int chunk = (n + 1023) >> 10;
    int start = tid * chunk;
    int end = min(start + chunk, n);
    int s = 0;
    for (int i = start; i < end; i++) s += g_deg[i];
    sums[tid] = s;
    __syncthreads();
    for (int off = 1; off < 1024; off <<= 1) {
        int v = (tid >= off) ? sums[tid - off] : 0;
        __syncthreads();
        sums[tid] += v;
        __syncthreads();
    }
    int prefix = (tid == 0) ? 0 : sums[tid - 1];
    for (int i = start; i < end; i++) {
        g_off[i] = prefix;
        g_cur[i] = prefix;
        prefix += g_deg[i];
    }
    if (tid == 1023) g_off[n] = sums[1023];
}

__global__ void fill_csr_k(const void* __restrict__ ew, int E, int N) {
    int e = blockIdx.x * blockDim.x + threadIdx.x;
    int ET = E + N;
    if (e >= ET) return;
    int src, dst;
    if (e < E) { src = edge_at(ew, e); dst = edge_at(ew, E + e); }
    else       { src = e - E; dst = src; }
    if ((unsigned)dst >= (unsigned)N || (unsigned)src >= (unsigned)N) return;
    int pos = atomicAdd(&g_cur[dst], 1);
    g_csr[pos] = src;
}

// ---------------- tiled fp32 GEMM: C[M,Nn] = A[M,K] @ B[K,Nn] ----------------
// BM=64 BN=64 BK=16, 256 threads, 4x4 per-thread microtile. Nn % 64 == 0, K % 16 == 0.
__device__ __forceinline__ void gemm_body(const float* __restrict__ A,
                                          const float* __restrict__ B,
                                          float* __restrict__ C,
                                          int M, int Nn, int K) {
    const int BM = 64, BN = 64, BK = 16, TM = 4, TN = 4;
    __shared__ float As[BK][BM];
    __shared__ float Bs[BK][BN];
    int tid = threadIdx.x;
    int tx = tid & 15;   // N direction
    int ty = tid >> 4;   // M direction
    int row0 = blockIdx.y * BM, col0 = blockIdx.x * BN;

    float acc[TM][TN];
#pragma unroll
    for (int i = 0; i < TM; i++)
#pragma unroll
        for (int j = 0; j < TN; j++) acc[i][j] = 0.f;

    for (int k0 = 0; k0 < K; k0 += BK) {
#pragma unroll 4
        for (int i = tid; i < BM * BK; i += 256) {
            int m = i >> 4, kk = i & 15;
            int r = row0 + m;
            As[kk][m] = (r < M) ? A[(long)r * K + k0 + kk] : 0.f;
        }
#pragma unroll 4
        for (int i = tid; i < BK * BN; i += 256) {
            int kk = i >> 6, nn = i & 63;
            Bs[kk][nn] = B[(long)(k0 + kk) * Nn + col0 + nn];
        }
        __syncthreads();
#pragma unroll
        for (int kk = 0; kk < BK; kk++) {
            float ra[TM], rb[TN];
#pragma unroll
            for (int i = 0; i < TM; i++) ra[i] = As[kk][ty * TM + i];
#pragma unroll
            for (int j = 0; j < TN; j++) rb[j] = Bs[kk][tx * TN + j];
#pragma unroll
            for (int i = 0; i < TM; i++)
#pragma unroll
                for (int j = 0; j < TN; j++) acc[i][j] += ra[i] * rb[j];
        }
        __syncthreads();
    }
#pragma unroll
    for (int i = 0; i < TM; i++) {
        int r = row0 + ty * TM + i;
        if (r >= M) continue;
#pragma unroll
        for (int j = 0; j < TN; j++)
            C[(long)r * Nn + col0 + tx * TN + j] = acc[i][j];
    }
}

// GEMM1: x @ W1 -> g_xw1
__global__ void gemm1_k(const float* __restrict__ A, const float* __restrict__ B, int M) {
    gemm_body(A, B, g_xw1, M, D1, FIN);
}

// GEMM2: g_h @ W2 -> g_h2
__global__ void gemm2_k(const float* __restrict__ B, int M) {
    gemm_body(g_h, B, g_h2, M, OUTC, D1);
}

// ---------------- attention coefficients, layer 1 ----------------
__global__ void alpha1_k(const float* __restrict__ a_src, const float* __restrict__ a_dst) {
    int n = blockIdx.x;
    int t = threadIdx.x;
    float v = g_xw1[n * D1 + t];
    float ps = v * a_src[t];
    float pd = v * a_dst[t];
#pragma unroll
    for (int o = 16; o; o >>= 1) {
        ps += __shfl_down_sync(0xffffffffu, ps, o);
        pd += __shfl_down_sync(0xffffffffu, pd, o);
    }
    if ((t & 31) == 0) {
        int h = t >> 5;
        g_as1[n * H1 + h] = ps;
        g_ad1[n * H1 + h] = pd;
    }
}

// ---------------- layer-1 aggregation + bias + ELU ----------------
__global__ void agg1_k(const float* __restrict__ b1) {
    int n = blockIdx.x;
    int t = threadIdx.x;
    int h = t >> 5;
    int c = t & 31;
    int beg = g_off[n], end = g_off[n + 1];
    float ad = g_ad1[n * H1 + h];

    float m = -1e30f, denom = 0.f;
    for (int k = beg; k < end; k++) {
        int s = g_csr[k];
        float e = g_as1[s * H1 + h] + ad;
        e = (e > 0.f) ? e : 0.2f * e;
        if (e > m) {
            denom = denom * __expf(m - e) + 1.f;
            m = e;
        } else {
            denom += __expf(e - m);
        }
    }
    float inv = 1.f / (denom + 1e-16f);

    float acc = 0.f;
    for (int k = beg; k < end; k++) {
        int s = g_csr[k];
        float e = g_as1[s * H1 + h] + ad;
        e = (e > 0.f) ? e : 0.2f * e;
        float w = __expf(e - m) * inv;
        acc += w * g_xw1[s * D1 + h * C1 + c];
    }
    acc += b1[t];
    acc = (acc > 0.f) ? acc : (__expf(acc) - 1.f);
    g_h[n * D1 + t] = acc;
}

// ---------------- attention coefficients, layer 2 (heads=1, C=64) ----------------
__global__ void alpha2_k(const float* __restrict__ a_src, const float* __restrict__ a_dst) {
    int n = blockIdx.x;
    int t = threadIdx.x;  // 64 threads
    float v = g_h2[n * OUTC + t];
    float ps = v * a_src[t];
    float pd = v * a_dst[t];
#pragma unroll
    for (int o = 16; o; o >>= 1) {
        ps += __shfl_down_sync(0xffffffffu, ps, o);
        pd += __shfl_down_sync(0xffffffffu, pd, o);
    }
    __shared__ float s0[2], s1[2];
    if ((t & 31) == 0) { s0[t >> 5] = ps; s1[t >> 5] = pd; }
    __syncthreads();
    if (t == 0) {
        g_as2[n] = s0[0] + s0[1];
        g_ad2[n] = s1[0] + s1[1];
    }
}

// ---------------- layer-2 aggregation + bias + log_softmax ----------------
__global__ void agg2_k(const float* __restrict__ b2, float* __restrict__ out) {
    int n = blockIdx.x;
    int t = threadIdx.x;  // 64 threads
    int beg = g_off[n], end = g_off[n + 1];
    float ad = g_ad2[n];

    float m = -1e30f, denom = 0.f;
    for (int k = beg; k < end; k++) {
        int s = g_csr[k];
        float e = g_as2[s] + ad;
        e = (e > 0.f) ? e : 0.2f * e;
        if (e > m) {
            denom = denom * __expf(m - e) + 1.f;
            m = e;
        } else {
            denom += __expf(e - m);
        }
    }
    float inv = 1.f / (denom + 1e-16f);

    float acc = 0.f;
    for (int k = beg; k < end; k++) {
        int s = g_csr[k];
        float e = g_as2[s] + ad;
        e = (e > 0.f) ? e : 0.2f * e;
        float w = __expf(e - m) * inv;
        acc += w * g_h2[s * OUTC + t];
    }
    acc += b2[t];

    __shared__ float sm[64];
    sm[t] = acc;
    __syncthreads();
#pragma unroll
    for (int o = 32; o >= 1; o >>= 1) {
        if (t < o) sm[t] = fmaxf(sm[t], sm[t + o]);
        __syncthreads();
    }
    float mx = sm[0];
    __syncthreads();
    sm[t] = __expf(acc - mx);
    __syncthreads();
#pragma unroll
    for (int o = 32; o >= 1; o >>= 1) {
        if (t < o) sm[t] += sm[t + o];
        __syncthreads();
    }
    float lse = mx + __logf(sm[0]);
    out[n * OUTC + t] = acc - lse;
}

// ---------------- launch ----------------
extern "C" void kernel_launch(void* const* d_in, const int* in_sizes, int n_in,
                              void* d_out, int out_size) {
    const float* x   = (const float*)d_in[0];
    const void*  ei  = d_in[1];                 // int32 or int64 node ids, detected on device
    const float* W1  = (const float*)d_in[2];
    const float* as1 = (const float*)d_in[3];
    const float* ad1 = (const float*)d_in[4];
    const float* b1  = (const float*)d_in[5];
    const float* W2  = (const float*)d_in[6];
    const float* as2 = (const float*)d_in[7];
    const float* ad2 = (const float*)d_in[8];
    const float* b2  = (const float*)d_in[9];
    float* out = (float*)d_out;

    int E = in_sizes[1] / 2;   // logical edge count (element count / 2, either dtype)
    int N = in_sizes[0] / FIN;
    int ET = E + N;

    // 0. detect edge dtype
    detect_k<<<1, 64>>>((const unsigned*)ei);

    // 1. CSR by destination
    zero_deg_k<<<(N + 255) / 256, 256>>>(N);
    count_deg_k<<<(ET + 255) / 256, 256>>>(ei, E, N);
    scan_k<<<1, 1024>>>(N);
    fill_csr_k<<<(ET + 255) / 256, 256>>>(ei, E, N);

    // 2. xw1 = x @ W1   [N,512]x[512,256]
    {
        dim3 grid(D1 / 64, (N + 63) / 64);
        gemm1_k<<<grid, 256>>>(x, W1, N);
    }

    // 3. per-node attention coefficients (layer 1)
    alpha1_k<<<N, 256>>>(as1, ad1);

    // 4. softmax-weighted aggregation + bias + ELU -> g_h
    agg1_k<<<N, 256>>>(b1);

    // 5. h2 = h @ W2   [N,256]x[256,64]
    {
        dim3 grid(OUTC / 64, (N + 63) / 64);
        gemm2_k<<<grid, 256>>>(W2, N);
    }

    // 6. layer-2 attention coefficients
    alpha2_k<<<N, 64>>>(as2, ad2);

    // 7. aggregation + bias + log_softmax -> out
    agg2_k<<<N, 64>>>(b2, out);
}

// round 4
// speedup vs baseline: 1.6639x; 1.6639x over previous
#include <cuda_runtime.h>
#include <math.h>
#include <stdint.h>

// ---------------- problem constants (fixed shapes) ----------------
#define MAXN 50000
#define MAXE 800000
#define FIN  512
#define D1   256      // H1 * C1
#define H1   8
#define C1   32
#define OUTC 64

// ---------------- scratch (static device globals; no allocation) ----------------
__device__ float g_xw1[MAXN * D1];
__device__ float g_h[MAXN * D1];
__device__ float g_h2[MAXN * OUTC];
__device__ float g_as1[MAXN * H1];
__device__ float g_ad1[MAXN * H1];
__device__ float g_as2[MAXN];
__device__ float g_ad2[MAXN];
__device__ int   g_deg[MAXN];
__device__ int   g_off[MAXN + 1];
__device__ int   g_cur[MAXN];
__device__ int   g_csr[MAXE + MAXN];
__device__ int   g_bsum[64];
__device__ int   g_is64;

// ---------------- edge dtype detection ----------------
__global__ void detect_k(const unsigned* __restrict__ ew) {
    int t = threadIdx.x;  // 64 threads
    unsigned w = ew[2 * t + 1];
    unsigned nz = __ballot_sync(0xffffffffu, w != 0u);
    __shared__ unsigned s[2];
    if ((t & 31) == 0) s[t >> 5] = nz;
    __syncthreads();
    if (t == 0) g_is64 = ((s[0] | s[1]) == 0u) ? 1 : 0;
}

__device__ __forceinline__ int edge_at(const void* ew, int idx) {
    if (g_is64) return (int)((const long long*)ew)[idx];
    return ((const int*)ew)[idx];
}

// ---------------- CSR construction ----------------
__global__ void zero_deg_k(int n) {
    int i = blockIdx.x * blockDim.x + threadIdx.x;
    if (i < n) g_deg[i] = 0;
}

__global__ void count_deg_k(const void* __restrict__ ew, int E, int N) {
    int e = blockIdx.x * blockDim.x + threadIdx.x;
    int ET = E + N;
    if (e >= ET) return;
    int dst = (e < E) ? edge_at(ew, E + e) : (e - E);
    if ((unsigned)dst < (unsigned)N) atomicAdd(&g_deg[dst], 1);
}

// ---- 3-phase scan: blockwise scan -> scan of block sums -> add-back ----
__global__ void scanA_k(int n) {
    __shared__ int s[1024];
    int t = threadIdx.x;
    int i = blockIdx.x * 1024 + t;
    int v = (i < n) ? g_deg[i] : 0;
    s[t] = v;
    __syncthreads();
#pragma unroll
    for (int off = 1; off < 1024; off <<= 1) {
        int tmp = (t >= off) ? s[t - off] : 0;
        __syncthreads();
        s[t] += tmp;
        __syncthreads();
    }
    if (i < n) g_off[i] = s[t] - v;          // exclusive within block
    if (t == 1023) g_bsum[blockIdx.x] = s[1023];
}

__global__ void scanB_k(int nb, int n) {
    // nb <= 64; two warps, shfl scan + cross-warp fix
    int t = threadIdx.x;
    int v = (t < nb) ? g_bsum[t] : 0;
    int lane = t & 31;
    int incl = v;
#pragma unroll
    for (int off = 1; off < 32; off <<= 1) {
        int u = __shfl_up_sync(0xffffffffu, incl, off);
        if (lane >= off) incl += u;
    }
    __shared__ int wt[2];
    if (lane == 31) wt[t >> 5] = incl;
    __syncthreads();
    int add = (t >= 32) ? wt[0] : 0;
    incl += add;
    if (t < nb) g_bsum[t] = incl - v;        // exclusive block offsets
    if (t == 63) g_off[n] = incl;            // grand total
}

__global__ void scanC_k(int n) {
    int t = threadIdx.x;
    int i = blockIdx.x * 1024 + t;
    if (i < n) {
        int o = g_off[i] + g_bsum[blockIdx.x];
        g_off[i] = o;
        g_cur[i] = o;
    }
}

__global__ void fill_csr_k(const void* __restrict__ ew, int E, int N) {
    int e = blockIdx.x * blockDim.x + threadIdx.x;
    int ET = E + N;
    if (e >= ET) return;
    int src, dst;
    if (e < E) { src = edge_at(ew, e); dst = edge_at(ew, E + e); }
    else       { src = e - E; dst = src; }
    if ((unsigned)dst >= (unsigned)N || (unsigned)src >= (unsigned)N) return;
    int pos = atomicAdd(&g_cur[dst], 1);
    g_csr[pos] = src;
}

// ---------------- TF32 tensor-core GEMM ----------------
// C[M,Nn] = A[M,K] @ B[K,Nn], fp32 in/out, tf32 mma.sync.m16n8k8, fp32 accum.
// BM=128 BN=64 BK=16, 256 threads = 8 warps (4 along M x 2 along N),
// warp tile 32x32 = 2 m-tiles x 4 n-tiles of m16n8.
#define GA_PAD 28   // As[m] row stride (floats): banks (28m+k)%32 all-distinct
#define GB_PAD 72   // Bs[k] row stride: banks (8k+n) distinct

__device__ __forceinline__ float to_tf32(float x) {
    uint32_t r;
    asm("cvt.rna.tf32.f32 %0, %1;" : "=r"(r) : "f"(x));
    return __uint_as_float(r);
}

__device__ __forceinline__ void mma_tf32(float* c, const uint32_t* a, const uint32_t* b) {
    asm volatile(
        "mma.sync.aligned.m16n8k8.row.col.f32.tf32.tf32.f32 "
        "{%0,%1,%2,%3}, {%4,%5,%6,%7}, {%8,%9}, {%0,%1,%2,%3};"
        : "+f"(c[0]), "+f"(c[1]), "+f"(c[2]), "+f"(c[3])
        : "r"(a[0]), "r"(a[1]), "r"(a[2]), "r"(a[3]), "r"(b[0]), "r"(b[1]));
}

__device__ __forceinline__ void gemm_tf32_body(const float* __restrict__ A,
                                               const float* __restrict__ B,
                                               float* __restrict__ C,
                                               int M, int Nn, int K) {
    __shared__ float As[128 * GA_PAD];   // [m][k], 14 KB
    __shared__ float Bs[16 * GB_PAD];    // [k][n], 4.6 KB

    int tid = threadIdx.x;
    int wid = tid >> 5, lane = tid & 31;
    int lq = lane >> 2, lr = lane & 3;
    int warp_m = wid & 3, warp_n = wid >> 2;
    int row0 = blockIdx.y * 128, col0 = blockIdx.x * 64;

    float acc[2][4][4];
#pragma unroll
    for (int i = 0; i < 2; i++)
#pragma unroll
        for (int j = 0; j < 4; j++)
#pragma unroll
            for (int q = 0; q < 4; q++) acc[i][j][q] = 0.f;

    int am = tid >> 1;             // 0..127
    int ak = (tid & 1) * 8;        // 0 or 8
    int bk = tid >> 4;             // 0..15
    int bn = (tid & 15) * 4;       // 0..60

    for (int k0 = 0; k0 < K; k0 += 16) {
        // load A tile 128x16 (zero-fill OOB rows)
        {
            int r = row0 + am;
            float4 v0 = make_float4(0.f, 0.f, 0.f, 0.f), v1 = v0;
            if (r < M) {
                const float4* p = (const float4*)(A + (long)r * K + k0 + ak);
                v0 = p[0]; v1 = p[1];
            }
            float* dst = As + am * GA_PAD + ak;
            dst[0] = to_tf32(v0.x); dst[1] = to_tf32(v0.y);
            dst[2] = to_tf32(v0.z); dst[3] = to_tf32(v0.w);
            dst[4] = to_tf32(v1.x); dst[5] = to_tf32(v1.y);
            dst[6] = to_tf32(v1.z); dst[7] = to_tf32(v1.w);
        }
        // load B tile 16x64
        {
            const float4* p = (const float4*)(B + (long)(k0 + bk) * Nn + col0 + bn);
            float4 v = p[0];
            float* dst = Bs + bk * GB_PAD + bn;
            dst[0] = to_tf32(v.x); dst[1] = to_tf32(v.y);
            dst[2] = to_tf32(v.z); dst[3] = to_tf32(v.w);
        }
        __syncthreads();

#pragma unroll
        for (int kk = 0; kk < 16; kk += 8) {
            uint32_t af[2][4], bf[4][2];
#pragma unroll
            for (int tm = 0; tm < 2; tm++) {
                int bm = warp_m * 32 + tm * 16;
                const float* ap = As + kk + lr;
                af[tm][0] = __float_as_uint(ap[(bm + lq) * GA_PAD]);
                af[tm][1] = __float_as_uint(ap[(bm + lq + 8) * GA_PAD]);
                af[tm][2] = __float_as_uint(ap[(bm + lq) * GA_PAD + 4]);
                af[tm][3] = __float_as_uint(ap[(bm + lq + 8) * GA_PAD + 4]);
            }
#pragma unroll
            for (int tn = 0; tn < 4; tn++) {
                int bb = warp_n * 32 + tn * 8 + lq;
                bf[tn][0] = __float_as_uint(Bs[(kk + lr) * GB_PAD + bb]);
                bf[tn][1] = __float_as_uint(Bs[(kk + lr + 4) * GB_PAD + bb]);
            }
#pragma unroll
            for (int tm = 0; tm < 2; tm++)
#pragma unroll
                for (int tn = 0; tn < 4; tn++)
                    mma_tf32(acc[tm][tn], af[tm], bf[tn]);
        }
        __syncthreads();
    }

    // epilogue: c0,c1 at (row, 2*lr), c2,c3 at (row+8, 2*lr)
#pragma unroll
    for (int tm = 0; tm < 2; tm++) {
        int r0 = row0 + warp_m * 32 + tm * 16 + lq;
#pragma unroll
        for (int tn = 0; tn < 4; tn++) {
            int c = col0 + warp_n * 32 + tn * 8 + 2 * lr;
            if (r0 < M) {
                float2* p = (float2*)(C + (long)r0 * Nn + c);
                *p = make_float2(acc[tm][tn][0], acc[tm][tn][1]);
            }
            if (r0 + 8 < M) {
                float2* p = (float2*)(C + (long)(r0 + 8) * Nn + c);
                *p = make_float2(acc[tm][tn][2], acc[tm][tn][3]);
            }
        }
    }
}

__global__ void gemm1_k(const float* __restrict__ A, const float* __restrict__ B, int M) {
    gemm_tf32_body(A, B, g_xw1, M, D1, FIN);
}
__global__ void gemm2_k(const float* __restrict__ B, int M) {
    gemm_tf32_body(g_h, B, g_h2, M, OUTC, D1);
}

// ---------------- attention coefficients, layer 1 ----------------
__global__ void alpha1_k(const float* __restrict__ a_src, const float* __restrict__ a_dst) {
    int n = blockIdx.x;
    int t = threadIdx.x;
    float v = g_xw1[n * D1 + t];
    float ps = v * a_src[t];
    float pd = v * a_dst[t];
#pragma unroll
    for (int o = 16; o; o >>= 1) {
        ps += __shfl_down_sync(0xffffffffu, ps, o);
        pd += __shfl_down_sync(0xffffffffu, pd, o);
    }
    if ((t & 31) == 0) {
        int h = t >> 5;
        g_as1[n * H1 + h] = ps;
        g_ad1[n * H1 + h] = pd;
    }
}

// ---------------- layer-1 aggregation + bias + ELU ----------------
__global__ void agg1_k(const float* __restrict__ b1) {
    int n = blockIdx.x;
    int t = threadIdx.x;
    int h = t >> 5;
    int c = t & 31;
    int beg = g_off[n], end = g_off[n + 1];
    float ad = g_ad1[n * H1 + h];

    float m = -1e30f, denom = 0.f;
    for (int k = beg; k < end; k++) {
        int s = g_csr[k];
        float e = g_as1[s * H1 + h] + ad;
        e = (e > 0.f) ? e : 0.2f * e;
        if (e > m) {
            denom = denom * __expf(m - e) + 1.f;
            m = e;
        } else {
            denom += __expf(e - m);
        }
    }
    float inv = 1.f / (denom + 1e-16f);

    float acc = 0.f;
    for (int k = beg; k < end; k++) {
        int s = g_csr[k];
        float e = g_as1[s * H1 + h] + ad;
        e = (e > 0.f) ? e : 0.2f * e;
        float w = __expf(e - m) * inv;
        acc += w * g_xw1[s * D1 + h * C1 + c];
    }
    acc += b1[t];
    acc = (acc > 0.f) ? acc : (__expf(acc) - 1.f);
    g_h[n * D1 + t] = acc;
}

// ---------------- attention coefficients, layer 2 ----------------
__global__ void alpha2_k(const float* __restrict__ a_src, const float* __restrict__ a_dst) {
    int n = blockIdx.x;
    int t = threadIdx.x;  // 64 threads
    float v = g_h2[n * OUTC + t];
    float ps = v * a_src[t];
    float pd = v * a_dst[t];
#pragma unroll
    for (int o = 16; o; o >>= 1) {
        ps += __shfl_down_sync(0xffffffffu, ps, o);
        pd += __shfl_down_sync(0xffffffffu, pd, o);
    }
    __shared__ float s0[2], s1[2];
    if ((t & 31) == 0) { s0[t >> 5] = ps; s1[t >> 5] = pd; }
    __syncthreads();
    if (t == 0) {
        g_as2[n] = s0[0] + s0[1];
        g_ad2[n] = s1[0] + s1[1];
    }
}

// ---------------- layer-2 aggregation + bias + log_softmax ----------------
__global__ void agg2_k(const float* __restrict__ b2, float* __restrict__ out) {
    int n = blockIdx.x;
    int t = threadIdx.x;  // 64 threads
    int beg = g_off[n], end = g_off[n + 1];
    float ad = g_ad2[n];

    float m = -1e30f, denom = 0.f;
    for (int k = beg; k < end; k++) {
        int s = g_csr[k];
        float e = g_as2[s] + ad;
        e = (e > 0.f) ? e : 0.2f * e;
        if (e > m) {
            denom = denom * __expf(m - e) + 1.f;
            m = e;
        } else {
            denom += __expf(e - m);
        }
    }
    float inv = 1.f / (denom + 1e-16f);

    float acc = 0.f;
    for (int k = beg; k < end; k++) {
        int s = g_csr[k];
        float e = g_as2[s] + ad;
        e = (e > 0.f) ? e : 0.2f * e;
        float w = __expf(e - m) * inv;
        acc += w * g_h2[s * OUTC + t];
    }
    acc += b2[t];

    __shared__ float sm[64];
    sm[t] = acc;
    __syncthreads();
#pragma unroll
    for (int o = 32; o >= 1; o >>= 1) {
        if (t < o) sm[t] = fmaxf(sm[t], sm[t + o]);
        __syncthreads();
    }
    float mx = sm[0];
    __syncthreads();
    sm[t] = __expf(acc - mx);
    __syncthreads();
#pragma unroll
    for (int o = 32; o >= 1; o >>= 1) {
        if (t < o) sm[t] += sm[t + o];
        __syncthreads();
    }
    float lse = mx + __logf(sm[0]);
    out[n * OUTC + t] = acc - lse;
}

// ---------------- launch ----------------
extern "C" void kernel_launch(void* const* d_in, const int* in_sizes, int n_in,
                              void* d_out, int out_size) {
    const float* x   = (const float*)d_in[0];
    const void*  ei  = d_in[1];
    const float* W1  = (const float*)d_in[2];
    const float* as1 = (const float*)d_in[3];
    const float* ad1 = (const float*)d_in[4];
    const float* b1  = (const float*)d_in[5];
    const float* W2  = (const float*)d_in[6];
    const float* as2 = (const float*)d_in[7];
    const float* ad2 = (const float*)d_in[8];
    const float* b2  = (const float*)d_in[9];
    float* out = (float*)d_out;

    int E = in_sizes[1] / 2;
    int N = in_sizes[0] / FIN;
    int ET = E + N;
    int nb = (N + 1023) / 1024;

    detect_k<<<1, 64>>>((const unsigned*)ei);

    zero_deg_k<<<(N + 255) / 256, 256>>>(N);
    count_deg_k<<<(ET + 255) / 256, 256>>>(ei, E, N);
    scanA_k<<<nb, 1024>>>(N);
    scanB_k<<<1, 64>>>(nb, N);
    scanC_k<<<nb, 1024>>>(N);
    fill_csr_k<<<(ET + 255) / 256, 256>>>(ei, E, N);

    {
        dim3 grid(D1 / 64, (N + 127) / 128);
        gemm1_k<<<grid, 256>>>(x, W1, N);
    }
    alpha1_k<<<N, 256>>>(as1, ad1);
    agg1_k<<<N, 256>>>(b1);
    {
        dim3 grid(OUTC / 64, (N + 127) / 128);
        gemm2_k<<<grid, 256>>>(W2, N);
    }
    alpha2_k<<<N, 64>>>(as2, ad2);
    agg2_k<<<N, 64>>>(b2, out);
}

// round 5
// speedup vs baseline: 2.5334x; 1.5226x over previous
#include <cuda_runtime.h>
#include <math.h>
#include <stdint.h>

// ---------------- problem constants (fixed shapes) ----------------
#define MAXN 50000
#define MAXE 800000
#define FIN  512
#define D1   256      // H1 * C1
#define H1   8
#define C1   32
#define OUTC 64

// ---------------- scratch (static device globals; no allocation) ----------------
__device__ float g_xw1[MAXN * D1];
__device__ float g_h[MAXN * D1];
__device__ float g_h2[MAXN * OUTC];
__device__ float g_as1[MAXN * H1];
__device__ float g_ad1[MAXN * H1];
__device__ float g_as2[MAXN];
__device__ float g_ad2[MAXN];
__device__ int   g_deg[MAXN];
__device__ int   g_off[MAXN + 1];
__device__ int   g_cur[MAXN];
__device__ int   g_csr[MAXE + MAXN];
__device__ int   g_bsum[64];
__device__ int   g_is64;

// ---------------- edge dtype detection ----------------
__global__ void detect_k(const unsigned* __restrict__ ew) {
    int t = threadIdx.x;  // 64 threads
    unsigned w = ew[2 * t + 1];
    unsigned nz = __ballot_sync(0xffffffffu, w != 0u);
    __shared__ unsigned s[2];
    if ((t & 31) == 0) s[t >> 5] = nz;
    __syncthreads();
    if (t == 0) g_is64 = ((s[0] | s[1]) == 0u) ? 1 : 0;
}

__device__ __forceinline__ int edge_at(const void* ew, int idx) {
    if (g_is64) return (int)((const long long*)ew)[idx];
    return ((const int*)ew)[idx];
}

// ---------------- CSR construction ----------------
__global__ void zero_deg_k(int n) {
    int i = blockIdx.x * blockDim.x + threadIdx.x;
    if (i < n) g_deg[i] = 0;
}

__global__ void count_deg_k(const void* __restrict__ ew, int E, int N) {
    int e = blockIdx.x * blockDim.x + threadIdx.x;
    int ET = E + N;
    if (e >= ET) return;
    int dst = (e < E) ? edge_at(ew, E + e) : (e - E);
    if ((unsigned)dst < (unsigned)N) atomicAdd(&g_deg[dst], 1);
}

// ---- 3-phase scan ----
__global__ void scanA_k(int n) {
    __shared__ int s[1024];
    int t = threadIdx.x;
    int i = blockIdx.x * 1024 + t;
    int v = (i < n) ? g_deg[i] : 0;
    s[t] = v;
    __syncthreads();
#pragma unroll
    for (int off = 1; off < 1024; off <<= 1) {
        int tmp = (t >= off) ? s[t - off] : 0;
        __syncthreads();
        s[t] += tmp;
        __syncthreads();
    }
    if (i < n) g_off[i] = s[t] - v;
    if (t == 1023) g_bsum[blockIdx.x] = s[1023];
}

__global__ void scanB_k(int nb, int n) {
    int t = threadIdx.x;
    int v = (t < nb) ? g_bsum[t] : 0;
    int lane = t & 31;
    int incl = v;
#pragma unroll
    for (int off = 1; off < 32; off <<= 1) {
        int u = __shfl_up_sync(0xffffffffu, incl, off);
        if (lane >= off) incl += u;
    }
    __shared__ int wt[2];
    if (lane == 31) wt[t >> 5] = incl;
    __syncthreads();
    int add = (t >= 32) ? wt[0] : 0;
    incl += add;
    if (t < nb) g_bsum[t] = incl - v;
    if (t == 63) g_off[n] = incl;
}

__global__ void scanC_k(int n) {
    int t = threadIdx.x;
    int i = blockIdx.x * 1024 + t;
    if (i < n) {
        int o = g_off[i] + g_bsum[blockIdx.x];
        g_off[i] = o;
        g_cur[i] = o;
    }
}

__global__ void fill_csr_k(const void* __restrict__ ew, int E, int N) {
    int e = blockIdx.x * blockDim.x + threadIdx.x;
    int ET = E + N;
    if (e >= ET) return;
    int src, dst;
    if (e < E) { src = edge_at(ew, e); dst = edge_at(ew, E + e); }
    else       { src = e - E; dst = src; }
    if ((unsigned)dst >= (unsigned)N || (unsigned)src >= (unsigned)N) return;
    int pos = atomicAdd(&g_cur[dst], 1);
    g_csr[pos] = src;
}

// ---------------- TF32 tensor-core GEMM ----------------
#define GA_PAD 28
#define GB_PAD 72

__device__ __forceinline__ float to_tf32(float x) {
    uint32_t r;
    asm("cvt.rna.tf32.f32 %0, %1;" : "=r"(r) : "f"(x));
    return __uint_as_float(r);
}

__device__ __forceinline__ void mma_tf32(float* c, const uint32_t* a, const uint32_t* b) {
    asm volatile(
        "mma.sync.aligned.m16n8k8.row.col.f32.tf32.tf32.f32 "
        "{%0,%1,%2,%3}, {%4,%5,%6,%7}, {%8,%9}, {%0,%1,%2,%3};"
        : "+f"(c[0]), "+f"(c[1]), "+f"(c[2]), "+f"(c[3])
        : "r"(a[0]), "r"(a[1]), "r"(a[2]), "r"(a[3]), "r"(b[0]), "r"(b[1]));
}

__device__ __forceinline__ void gemm_tf32_body(const float* __restrict__ A,
                                               const float* __restrict__ B,
                                               float* __restrict__ C,
                                               int M, int Nn, int K) {
    __shared__ float As[128 * GA_PAD];
    __shared__ float Bs[16 * GB_PAD];

    int tid = threadIdx.x;
    int wid = tid >> 5, lane = tid & 31;
    int lq = lane >> 2, lr = lane & 3;
    int warp_m = wid & 3, warp_n = wid >> 2;
    int row0 = blockIdx.y * 128, col0 = blockIdx.x * 64;

    float acc[2][4][4];
#pragma unroll
    for (int i = 0; i < 2; i++)
#pragma unroll
        for (int j = 0; j < 4; j++)
#pragma unroll
            for (int q = 0; q < 4; q++) acc[i][j][q] = 0.f;

    int am = tid >> 1;
    int ak = (tid & 1) * 8;
    int bk = tid >> 4;
    int bn = (tid & 15) * 4;

    for (int k0 = 0; k0 < K; k0 += 16) {
        {
            int r = row0 + am;
            float4 v0 = make_float4(0.f, 0.f, 0.f, 0.f), v1 = v0;
            if (r < M) {
                const float4* p = (const float4*)(A + (long)r * K + k0 + ak);
                v0 = p[0]; v1 = p[1];
            }
            float* dst = As + am * GA_PAD + ak;
            dst[0] = to_tf32(v0.x); dst[1] = to_tf32(v0.y);
            dst[2] = to_tf32(v0.z); dst[3] = to_tf32(v0.w);
            dst[4] = to_tf32(v1.x); dst[5] = to_tf32(v1.y);
            dst[6] = to_tf32(v1.z); dst[7] = to_tf32(v1.w);
        }
        {
            const float4* p = (const float4*)(B + (long)(k0 + bk) * Nn + col0 + bn);
            float4 v = p[0];
            float* dst = Bs + bk * GB_PAD + bn;
            dst[0] = to_tf32(v.x); dst[1] = to_tf32(v.y);
            dst[2] = to_tf32(v.z); dst[3] = to_tf32(v.w);
        }
        __syncthreads();

#pragma unroll
        for (int kk = 0; kk < 16; kk += 8) {
            uint32_t af[2][4], bf[4][2];
#pragma unroll
            for (int tm = 0; tm < 2; tm++) {
                int bm = warp_m * 32 + tm * 16;
                const float* ap = As + kk + lr;
                af[tm][0] = __float_as_uint(ap[(bm + lq) * GA_PAD]);
                af[tm][1] = __float_as_uint(ap[(bm + lq + 8) * GA_PAD]);
                af[tm][2] = __float_as_uint(ap[(bm + lq) * GA_PAD + 4]);
                af[tm][3] = __float_as_uint(ap[(bm + lq + 8) * GA_PAD + 4]);
            }
#pragma unroll
            for (int tn = 0; tn < 4; tn++) {
                int bb = warp_n * 32 + tn * 8 + lq;
                bf[tn][0] = __float_as_uint(Bs[(kk + lr) * GB_PAD + bb]);
                bf[tn][1] = __float_as_uint(Bs[(kk + lr + 4) * GB_PAD + bb]);
            }
#pragma unroll
            for (int tm = 0; tm < 2; tm++)
#pragma unroll
                for (int tn = 0; tn < 4; tn++)
                    mma_tf32(acc[tm][tn], af[tm], bf[tn]);
        }
        __syncthreads();
    }

#pragma unroll
    for (int tm = 0; tm < 2; tm++) {
        int r0 = row0 + warp_m * 32 + tm * 16 + lq;
#pragma unroll
        for (int tn = 0; tn < 4; tn++) {
            int c = col0 + warp_n * 32 + tn * 8 + 2 * lr;
            if (r0 < M) {
                float2* p = (float2*)(C + (long)r0 * Nn + c);
                *p = make_float2(acc[tm][tn][0], acc[tm][tn][1]);
            }
            if (r0 + 8 < M) {
                float2* p = (float2*)(C + (long)(r0 + 8) * Nn + c);
                *p = make_float2(acc[tm][tn][2], acc[tm][tn][3]);
            }
        }
    }
}

__global__ void gemm1_k(const float* __restrict__ A, const float* __restrict__ B, int M) {
    gemm_tf32_body(A, B, g_xw1, M, D1, FIN);
}
__global__ void gemm2_k(const float* __restrict__ B, int M) {
    gemm_tf32_body(g_h, B, g_h2, M, OUTC, D1);
}

// ---------------- attention coefficients, layer 1 ----------------
__global__ void alpha1_k(const float* __restrict__ a_src, const float* __restrict__ a_dst) {
    int n = blockIdx.x;
    int t = threadIdx.x;
    float v = g_xw1[n * D1 + t];
    float ps = v * a_src[t];
    float pd = v * a_dst[t];
#pragma unroll
    for (int o = 16; o; o >>= 1) {
        ps += __shfl_down_sync(0xffffffffu, ps, o);
        pd += __shfl_down_sync(0xffffffffu, pd, o);
    }
    if ((t & 31) == 0) {
        int h = t >> 5;
        g_as1[n * H1 + h] = ps;
        g_ad1[n * H1 + h] = pd;
    }
}

// ---------------- layer-1 aggregation: one WARP per node ----------------
// lanes 0..7 carry per-head softmax state; all 32 lanes accumulate 8 channels each.
__global__ void agg1_k(const float* __restrict__ b1, int N) {
    int warp = (blockIdx.x * blockDim.x + threadIdx.x) >> 5;
    if (warp >= N) return;
    int n = warp;
    int lane = threadIdx.x & 31;
    int beg = g_off[n], end = g_off[n + 1];

    float ad = (lane < H1) ? g_ad1[n * H1 + lane] : 0.f;

    // pass 1: per-head online softmax stats in lanes 0..7
    float m = -1e30f, denom = 0.f;
    for (int k = beg; k < end; k++) {
        int s = g_csr[k];
        float as = (lane < H1) ? g_as1[s * H1 + lane] : 0.f;
        float e = as + ad;
        e = (e > 0.f) ? e : 0.2f * e;
        if (e > m) {
            denom = denom * __expf(m - e) + 1.f;
            m = e;
        } else {
            denom += __expf(e - m);
        }
    }
    float inv = 1.f / (denom + 1e-16f);

    // pass 2: weighted gather; lane c accumulates channel c of each head
    float acc[H1];
#pragma unroll
    for (int h = 0; h < H1; h++) acc[h] = 0.f;

    for (int k = beg; k < end; k++) {
        int s = g_csr[k];
        float as = (lane < H1) ? g_as1[s * H1 + lane] : 0.f;
        float e = as + ad;
        e = (e > 0.f) ? e : 0.2f * e;
        float w = __expf(e - m) * inv;   // valid in lanes 0..7
        const float* row = g_xw1 + s * D1;
#pragma unroll
        for (int h = 0; h < H1; h++) {
            float wh = __shfl_sync(0xffffffffu, w, h);
            acc[h] = fmaf(wh, row[h * C1 + lane], acc[h]);
        }
    }

#pragma unroll
    for (int h = 0; h < H1; h++) {
        float v = acc[h] + b1[h * C1 + lane];
        v = (v > 0.f) ? v : (__expf(v) - 1.f);   // ELU
        g_h[n * D1 + h * C1 + lane] = v;
    }
}

// ---------------- attention coefficients, layer 2 ----------------
__global__ void alpha2_k(const float* __restrict__ a_src, const float* __restrict__ a_dst) {
    int n = blockIdx.x;
    int t = threadIdx.x;  // 64 threads
    float v = g_h2[n * OUTC + t];
    float ps = v * a_src[t];
    float pd = v * a_dst[t];
#pragma unroll
    for (int o = 16; o; o >>= 1) {
        ps += __shfl_down_sync(0xffffffffu, ps, o);
        pd += __shfl_down_sync(0xffffffffu, pd, o);
    }
    __shared__ float s0[2], s1[2];
    if ((t & 31) == 0) { s0[t >> 5] = ps; s1[t >> 5] = pd; }
    __syncthreads();
    if (t == 0) {
        g_as2[n] = s0[0] + s0[1];
        g_ad2[n] = s1[0] + s1[1];
    }
}

// ---------------- layer-2 aggregation + bias + log_softmax: one WARP per node ----
__global__ void agg2_k(const float* __restrict__ b2, float* __restrict__ out, int N) {
    int warp = (blockIdx.x * blockDim.x + threadIdx.x) >> 5;
    if (warp >= N) return;
    int n = warp;
    int lane = threadIdx.x & 31;
    int beg = g_off[n], end = g_off[n + 1];
    float ad = g_ad2[n];

    float m = -1e30f, denom = 0.f;
    for (int k = beg; k < end; k++) {
        int s = g_csr[k];
        float e = g_as2[s] + ad;           // uniform across lanes
        e = (e > 0.f) ? e : 0.2f * e;
        if (e > m) {
            denom = denom * __expf(m - e) + 1.f;
            m = e;
        } else {
            denom += __expf(e - m);
        }
    }
    float inv = 1.f / (denom + 1e-16f);

    float a0 = 0.f, a1 = 0.f;
    for (int k = beg; k < end; k++) {
        int s = g_csr[k];
        float e = g_as2[s] + ad;
        e = (e > 0.f) ? e : 0.2f * e;
        float w = __expf(e - m) * inv;
        const float* row = g_h2 + s * OUTC;
        a0 = fmaf(w, row[lane], a0);
        a1 = fmaf(w, row[32 + lane], a1);
    }
    a0 += b2[lane];
    a1 += b2[32 + lane];

    // log_softmax over 64 values held as (a0, a1) across the warp
    float mx = fmaxf(a0, a1);
#pragma unroll
    for (int o = 16; o; o >>= 1) mx = fmaxf(mx, __shfl_xor_sync(0xffffffffu, mx, o));
    float sum = __expf(a0 - mx) + __expf(a1 - mx);
#pragma unroll
    for (int o = 16; o; o >>= 1) sum += __shfl_xor_sync(0xffffffffu, sum, o);
    float lse = mx + __logf(sum);
    out[n * OUTC + lane] = a0 - lse;
    out[n * OUTC + 32 + lane] = a1 - lse;
}

// ---------------- launch ----------------
extern "C" void kernel_launch(void* const* d_in, const int* in_sizes, int n_in,
                              void* d_out, int out_size) {
    const float* x   = (const float*)d_in[0];
    const void*  ei  = d_in[1];
    const float* W1  = (const float*)d_in[2];
    const float* as1 = (const float*)d_in[3];
    const float* ad1 = (const float*)d_in[4];
    const float* b1  = (const float*)d_in[5];
    const float* W2  = (const float*)d_in[6];
    const float* as2 = (const float*)d_in[7];
    const float* ad2 = (const float*)d_in[8];
    const float* b2  = (const float*)d_in[9];
    float* out = (float*)d_out;

    int E = in_sizes[1] / 2;
    int N = in_sizes[0] / FIN;
    int ET = E + N;
    int nb = (N + 1023) / 1024;

    detect_k<<<1, 64>>>((const unsigned*)ei);

    zero_deg_k<<<(N + 255) / 256, 256>>>(N);
    count_deg_k<<<(ET + 255) / 256, 256>>>(ei, E, N);
    scanA_k<<<nb, 1024>>>(N);
    scanB_k<<<1, 64>>>(nb, N);
    scanC_k<<<nb, 1024>>>(N);
    fill_csr_k<<<(ET + 255) / 256, 256>>>(ei, E, N);

    {
        dim3 grid(D1 / 64, (N + 127) / 128);
        gemm1_k<<<grid, 256>>>(x, W1, N);
    }
    alpha1_k<<<N, 256>>>(as1, ad1);
    agg1_k<<<(N * 32 + 255) / 256, 256>>>(b1, N);
    {
        dim3 grid(OUTC / 64, (N + 127) / 128);
        gemm2_k<<<grid, 256>>>(W2, N);
    }
    alpha2_k<<<N, 64>>>(as2, ad2);
    agg2_k<<<(N * 32 + 255) / 256, 256>>>(b2, out, N);
}

// round 7
// speedup vs baseline: 2.8457x; 1.1233x over previous
#include <cuda_runtime.h>
#include <math.h>
#include <stdint.h>

// ---------------- problem constants (fixed shapes) ----------------
#define MAXN 50000
#define MAXE 800000
#define FIN  512
#define D1   256      // H1 * C1
#define H1   8
#define C1   32
#define OUTC 64

// ---------------- scratch ----------------
__device__ float g_xw1[MAXN * D1];
__device__ float g_h[MAXN * D1];
__device__ float g_h2[MAXN * OUTC];
__device__ float g_as1[MAXN * H1];
__device__ float g_ad1[MAXN * H1];
__device__ float g_as2[MAXN];
__device__ float g_ad2[MAXN];
__device__ int   g_deg[MAXN];
__device__ int   g_off[MAXN + 1];
__device__ int   g_cur[MAXN];
__device__ int   g_csr[MAXE + MAXN];
__device__ int   g_bsum[64];
__device__ int   g_is64;

// ---------------- edge dtype detection ----------------
__global__ void detect_k(const unsigned* __restrict__ ew) {
    int t = threadIdx.x;  // 64 threads
    unsigned w = ew[2 * t + 1];
    unsigned nz = __ballot_sync(0xffffffffu, w != 0u);
    __shared__ unsigned s[2];
    if ((t & 31) == 0) s[t >> 5] = nz;
    __syncthreads();
    if (t == 0) g_is64 = ((s[0] | s[1]) == 0u) ? 1 : 0;
}

__device__ __forceinline__ int edge_at(const void* ew, int idx) {
    if (g_is64) return (int)((const long long*)ew)[idx];
    return ((const int*)ew)[idx];
}

// ---------------- CSR construction ----------------
__global__ void zero_deg_k(int n) {
    int i = blockIdx.x * blockDim.x + threadIdx.x;
    if (i < n) g_deg[i] = 0;
}

__global__ void count_deg_k(const void* __restrict__ ew, int E, int N) {
    int e = blockIdx.x * blockDim.x + threadIdx.x;
    int ET = E + N;
    if (e >= ET) return;
    int dst = (e < E) ? edge_at(ew, E + e) : (e - E);
    if ((unsigned)dst < (unsigned)N) atomicAdd(&g_deg[dst], 1);
}

__global__ void scanA_k(int n) {
    __shared__ int s[1024];
    int t = threadIdx.x;
    int i = blockIdx.x * 1024 + t;
    int v = (i < n) ? g_deg[i] : 0;
    s[t] = v;
    __syncthreads();
#pragma unroll
    for (int off = 1; off < 1024; off <<= 1) {
        int tmp = (t >= off) ? s[t - off] : 0;
        __syncthreads();
        s[t] += tmp;
        __syncthreads();
    }
    if (i < n) g_off[i] = s[t] - v;
    if (t == 1023) g_bsum[blockIdx.x] = s[1023];
}

__global__ void scanB_k(int nb, int n) {
    int t = threadIdx.x;
    int v = (t < nb) ? g_bsum[t] : 0;
    int lane = t & 31;
    int incl = v;
#pragma unroll
    for (int off = 1; off < 32; off <<= 1) {
        int u = __shfl_up_sync(0xffffffffu, incl, off);
        if (lane >= off) incl += u;
    }
    __shared__ int wt[2];
    if (lane == 31) wt[t >> 5] = incl;
    __syncthreads();
    int add = (t >= 32) ? wt[0] : 0;
    incl += add;
    if (t < nb) g_bsum[t] = incl - v;
    if (t == 63) g_off[n] = incl;
}

__global__ void scanC_k(int n) {
    int t = threadIdx.x;
    int i = blockIdx.x * 1024 + t;
    if (i < n) {
        int o = g_off[i] + g_bsum[blockIdx.x];
        g_off[i] = o;
        g_cur[i] = o;
    }
}

__global__ void fill_csr_k(const void* __restrict__ ew, int E, int N) {
    int e = blockIdx.x * blockDim.x + threadIdx.x;
    int ET = E + N;
    if (e >= ET) return;
    int src, dst;
    if (e < E) { src = edge_at(ew, e); dst = edge_at(ew, E + e); }
    else       { src = e - E; dst = src; }
    if ((unsigned)dst >= (unsigned)N || (unsigned)src >= (unsigned)N) return;
    int pos = atomicAdd(&g_cur[dst], 1);
    g_csr[pos] = src;
}

// ---------------- TF32 tensor-core GEMM, 2-stage cp.async pipeline ----------------
// BM=128 BN=64 BK=16; 256 threads = 8 warps (4 M x 2 N); warp tile 32x32.
#define GA_PAD 20   // floats; 80B row stride: 16B-aligned, (20*lq+lr)%32 all-distinct
#define GB_PAD 72   // floats; 288B row stride: 16B-aligned, conflict-free

__device__ __forceinline__ uint32_t cvt_tf32(uint32_t x) {
    uint32_t r;
    asm("cvt.rna.tf32.f32 %0, %1;" : "=r"(r) : "f"(__uint_as_float(x)));
    return r;
}

__device__ __forceinline__ void mma_tf32(float* c, const uint32_t* a, const uint32_t* b) {
    asm volatile(
        "mma.sync.aligned.m16n8k8.row.col.f32.tf32.tf32.f32 "
        "{%0,%1,%2,%3}, {%4,%5,%6,%7}, {%8,%9}, {%0,%1,%2,%3};"
        : "+f"(c[0]), "+f"(c[1]), "+f"(c[2]), "+f"(c[3])
        : "r"(a[0]), "r"(a[1]), "r"(a[2]), "r"(a[3]), "r"(b[0]), "r"(b[1]));
}

__device__ __forceinline__ void cp16(uint32_t smem, const float* gptr, bool valid) {
    int sz = valid ? 16 : 0;
    asm volatile("cp.async.cg.shared.global [%0], [%1], 16, %2;"
                 :: "r"(smem), "l"(gptr), "r"(sz));
}

__device__ __forceinline__ void gemm_tf32_body(const float* __restrict__ A,
                                               const float* __restrict__ B,
                                               float* __restrict__ C,
                                               int M, int Nn, int K) {
    __shared__ float As[2][128 * GA_PAD];   // 2 x 10.0 KB
    __shared__ float Bs[2][16 * GB_PAD];    // 2 x 4.5 KB

    int tid = threadIdx.x;
    int wid = tid >> 5, lane = tid & 31;
    int lq = lane >> 2, lr = lane & 3;
    int warp_m = wid & 3, warp_n = wid >> 2;
    int row0 = blockIdx.y * 128, col0 = blockIdx.x * 64;

    uint32_t as_base = (uint32_t)__cvta_generic_to_shared(&As[0][0]);
    uint32_t bs_base = (uint32_t)__cvta_generic_to_shared(&Bs[0][0]);
    const uint32_t as_stage = 128 * GA_PAD * 4;
    const uint32_t bs_stage = 16 * GB_PAD * 4;

    float acc[2][4][4];
#pragma unroll
    for (int i = 0; i < 2; i++)
#pragma unroll
        for (int j = 0; j < 4; j++)
#pragma unroll
            for (int q = 0; q < 4; q++) acc[i][j][q] = 0.f;

    // A: 512 float4 per tile -> 2 per thread. idx = tid + 256*u; row=idx>>2, f4=idx&3.
    // B: 256 float4 per tile -> 1 per thread. row=tid>>4, f4=tid&15.
    int a_row[2], a_col[2];
#pragma unroll
    for (int u = 0; u < 2; u++) {
        int idx = tid + 256 * u;
        a_row[u] = idx >> 2;
        a_col[u] = (idx & 3) * 4;
    }
    int b_row = tid >> 4, b_col = (tid & 15) * 4;

    int nk = K >> 4;

    auto issue = [&](int kt, int stage) {
#pragma unroll
        for (int u = 0; u < 2; u++) {
            int r = row0 + a_row[u];
            bool v = (r < M);
            const float* gp = A + (long)(v ? r : 0) * K + (kt << 4) + a_col[u];
            cp16(as_base + stage * as_stage + (a_row[u] * GA_PAD + a_col[u]) * 4, gp, v);
        }
        const float* gp = B + (long)((kt << 4) + b_row) * Nn + col0 + b_col;
        cp16(bs_base + stage * bs_stage + (b_row * GB_PAD + b_col) * 4, gp, true);
        asm volatile("cp.async.commit_group;");
    };

    issue(0, 0);

    for (int kt = 0; kt < nk; kt++) {
        int stage = kt & 1;
        if (kt + 1 < nk) {
            issue(kt + 1, stage ^ 1);
            asm volatile("cp.async.wait_group 1;");
        } else {
            asm volatile("cp.async.wait_group 0;");
        }
        __syncthreads();

        const float* Asb = &As[stage][0];
        const float* Bsb = &Bs[stage][0];
#pragma unroll
        for (int kk = 0; kk < 16; kk += 8) {
            uint32_t af[2][4], bf[4][2];
#pragma unroll
            for (int tm = 0; tm < 2; tm++) {
                int bm = warp_m * 32 + tm * 16;
                const float* ap = Asb + kk + lr;
                af[tm][0] = cvt_tf32(__float_as_uint(ap[(bm + lq) * GA_PAD]));
                af[tm][1] = cvt_tf32(__float_as_uint(ap[(bm + lq + 8) * GA_PAD]));
                af[tm][2] = cvt_tf32(__float_as_uint(ap[(bm + lq) * GA_PAD + 4]));
                af[tm][3] = cvt_tf32(__float_as_uint(ap[(bm + lq + 8) * GA_PAD + 4]));
            }
#pragma unroll
            for (int tn = 0; tn < 4; tn++) {
                int bb = warp_n * 32 + tn * 8 + lq;
                bf[tn][0] = cvt_tf32(__float_as_uint(Bsb[(kk + lr) * GB_PAD + bb]));
                bf[tn][1] = cvt_tf32(__float_as_uint(Bsb[(kk + lr + 4) * GB_PAD + bb]));
            }
#pragma unroll
            for (int tm = 0; tm < 2; tm++)
#pragma unroll
                for (int tn = 0; tn < 4; tn++)
                    mma_tf32(acc[tm][tn], af[tm], bf[tn]);
        }
        __syncthreads();
    }

#pragma unroll
    for (int tm = 0; tm < 2; tm++) {
        int r0 = row0 + warp_m * 32 + tm * 16 + lq;
#pragma unroll
        for (int tn = 0; tn < 4; tn++) {
            int c = col0 + warp_n * 32 + tn * 8 + 2 * lr;
            if (r0 < M) {
                float2* p = (float2*)(C + (long)r0 * Nn + c);
                *p = make_float2(acc[tm][tn][0], acc[tm][tn][1]);
            }
            if (r0 + 8 < M) {
                float2* p = (float2*)(C + (long)(r0 + 8) * Nn + c);
                *p = make_float2(acc[tm][tn][2], acc[tm][tn][3]);
            }
        }
    }
}

__global__ void gemm1_k(const float* __restrict__ A, const float* __restrict__ B, int M) {
    gemm_tf32_body(A, B, g_xw1, M, D1, FIN);
}
__global__ void gemm2_k(const float* __restrict__ B, int M) {
    gemm_tf32_body(g_h, B, g_h2, M, OUTC, D1);
}

// ---------------- attention coefficients, layer 1 ----------------
__global__ void alpha1_k(const float* __restrict__ a_src, const float* __restrict__ a_dst) {
    int n = blockIdx.x;
    int t = threadIdx.x;
    float v = g_xw1[n * D1 + t];
    float ps = v * a_src[t];
    float pd = v * a_dst[t];
#pragma unroll
    for (int o = 16; o; o >>= 1) {
        ps += __shfl_down_sync(0xffffffffu, ps, o);
        pd += __shfl_down_sync(0xffffffffu, pd, o);
    }
    if ((t & 31) == 0) {
        int h = t >> 5;
        g_as1[n * H1 + h] = ps;
        g_ad1[n * H1 + h] = pd;
    }
}

// ---------------- layer-1 aggregation: one WARP per node ----------------
__global__ void agg1_k(const float* __restrict__ b1, int N) {
    int warp = (blockIdx.x * blockDim.x + threadIdx.x) >> 5;
    if (warp >= N) return;
    int n = warp;
    int lane = threadIdx.x & 31;
    int beg = g_off[n], end = g_off[n + 1];

    float ad = (lane < H1) ? g_ad1[n * H1 + lane] : 0.f;

    float m = -1e30f, denom = 0.f;
    for (int k = beg; k < end; k++) {
        int s = g_csr[k];
        float as = (lane < H1) ? g_as1[s * H1 + lane] : 0.f;
        float e = as + ad;
        e = (e > 0.f) ? e : 0.2f * e;
        if (e > m) {
            denom = denom * __expf(m - e) + 1.f;
            m = e;
        } else {
            denom += __expf(e - m);
        }
    }
    float inv = 1.f / (denom + 1e-16f);

    float acc[H1];
#pragma unroll
    for (int h = 0; h < H1; h++) acc[h] = 0.f;

    for (int k = beg; k < end; k++) {
        int s = g_csr[k];
        float as = (lane < H1) ? g_as1[s * H1 + lane] : 0.f;
        float e = as + ad;
        e = (e > 0.f) ? e : 0.2f * e;
        float w = __expf(e - m) * inv;
        const float* row = g_xw1 + s * D1;
#pragma unroll
        for (int h = 0; h < H1; h++) {
            float wh = __shfl_sync(0xffffffffu, w, h);
            acc[h] = fmaf(wh, row[h * C1 + lane], acc[h]);
        }
    }

#pragma unroll
    for (int h = 0; h < H1; h++) {
        float v = acc[h] + b1[h * C1 + lane];
        v = (v > 0.f) ? v : (__expf(v) - 1.f);
        g_h[n * D1 + h * C1 + lane] = v;
    }
}

// ---------------- attention coefficients, layer 2 ----------------
__global__ void alpha2_k(const float* __restrict__ a_src, const float* __restrict__ a_dst) {
    int n = blockIdx.x;
    int t = threadIdx.x;  // 64 threads
    float v = g_h2[n * OUTC + t];
    float ps = v * a_src[t];
    float pd = v * a_dst[t];
#pragma unroll
    for (int o = 16; o; o >>= 1) {
        ps += __shfl_down_sync(0xffffffffu, ps, o);
        pd += __shfl_down_sync(0xffffffffu, pd, o);
    }
    __shared__ float s0[2], s1[2];
    if ((t & 31) == 0) { s0[t >> 5] = ps; s1[t >> 5] = pd; }
    __syncthreads();
    if (t == 0) {
        g_as2[n] = s0[0] + s0[1];
        g_ad2[n] = s1[0] + s1[1];
    }
}

// ---------------- layer-2 aggregation + bias + log_softmax ----------------
__global__ void agg2_k(const float* __restrict__ b2, float* __restrict__ out, int N) {
    int warp = (blockIdx.x * blockDim.x + threadIdx.x) >> 5;
    if (warp >= N) return;
    int n = warp;
    int lane = threadIdx.x & 31;
    int beg = g_off[n], end = g_off[n + 1];
    float ad = g_ad2[n];

    float m = -1e30f, denom = 0.f;
    for (int k = beg; k < end; k++) {
        int s = g_csr[k];
        float e = g_as2[s] + ad;
        e = (e > 0.f) ? e : 0.2f * e;
        if (e > m) {
            denom = denom * __expf(m - e) + 1.f;
            m = e;
        } else {
            denom += __expf(e - m);
        }
    }
    float inv = 1.f / (denom + 1e-16f);

    float a0 = 0.f, a1 = 0.f;
    for (int k = beg; k < end; k++) {
        int s = g_csr[k];
        float e = g_as2[s] + ad;
        e = (e > 0.f) ? e : 0.2f * e;
        float w = __expf(e - m) * inv;
        const float* row = g_h2 + s * OUTC;
        a0 = fmaf(w, row[lane], a0);
        a1 = fmaf(w, row[32 + lane], a1);
    }
    a0 += b2[lane];
    a1 += b2[32 + lane];

    float mx = fmaxf(a0, a1);
#pragma unroll
    for (int o = 16; o; o >>= 1) mx = fmaxf(mx, __shfl_xor_sync(0xffffffffu, mx, o));
    float sum = __expf(a0 - mx) + __expf(a1 - mx);
#pragma unroll
    for (int o = 16; o; o >>= 1) sum += __shfl_xor_sync(0xffffffffu, sum, o);
    float lse = mx + __logf(sum);
    out[n * OUTC + lane] = a0 - lse;
    out[n * OUTC + 32 + lane] = a1 - lse;
}

// ---------------- launch ----------------
extern "C" void kernel_launch(void* const* d_in, const int* in_sizes, int n_in,
                              void* d_out, int out_size) {
    const float* x   = (const float*)d_in[0];
    const void*  ei  = d_in[1];
    const float* W1  = (const float*)d_in[2];
    const float* as1 = (const float*)d_in[3];
    const float* ad1 = (const float*)d_in[4];
    const float* b1  = (const float*)d_in[5];
    const float* W2  = (const float*)d_in[6];
    const float* as2 = (const float*)d_in[7];
    const float* ad2 = (const float*)d_in[8];
    const float* b2  = (const float*)d_in[9];
    float* out = (float*)d_out;

    int E = in_sizes[1] / 2;
    int N = in_sizes[0] / FIN;
    int ET = E + N;
    int nb = (N + 1023) / 1024;

    detect_k<<<1, 64>>>((const unsigned*)ei);

    zero_deg_k<<<(N + 255) / 256, 256>>>(N);
    count_deg_k<<<(ET + 255) / 256, 256>>>(ei, E, N);
    scanA_k<<<nb, 1024>>>(N);
    scanB_k<<<1, 64>>>(nb, N);
    scanC_k<<<nb, 1024>>>(N);
    fill_csr_k<<<(ET + 255) / 256, 256>>>(ei, E, N);

    {
        dim3 grid(D1 / 64, (N + 127) / 128);
        gemm1_k<<<grid, 256>>>(x, W1, N);
    }
    alpha1_k<<<N, 256>>>(as1, ad1);
    agg1_k<<<(N * 32 + 255) / 256, 256>>>(b1, N);
    {
        dim3 grid(OUTC / 64, (N + 127) / 128);
        gemm2_k<<<grid, 256>>>(W2, N);
    }
    alpha2_k<<<N, 64>>>(as2, ad2);
    agg2_k<<<(N * 32 + 255) / 256, 256>>>(b2, out, N);
}

// round 8
// speedup vs baseline: 3.3164x; 1.1654x over previous
#include <cuda_runtime.h>
#include <math.h>
#include <stdint.h>

// ---------------- problem constants (fixed shapes) ----------------
#define MAXN 50000
#define MAXE 800000
#define FIN  512
#define D1   256      // H1 * C1
#define H1   8
#define C1   32
#define OUTC 64

// ---------------- scratch ----------------
__device__ float g_xw1[MAXN * D1];
__device__ float g_h[MAXN * D1];
__device__ float g_h2[MAXN * OUTC];
__device__ float g_as1[MAXN * H1];
__device__ float g_ad1[MAXN * H1];
__device__ float g_as2[MAXN];
__device__ float g_ad2[MAXN];
__device__ int   g_deg[MAXN];
__device__ int   g_off[MAXN + 1];
__device__ int   g_cur[MAXN];
__device__ int   g_csr[MAXE + MAXN];
__device__ int   g_bsum[64];
__device__ int   g_is64;

// ---------------- edge dtype detection ----------------
__global__ void detect_k(const unsigned* __restrict__ ew) {
    int t = threadIdx.x;  // 64 threads
    unsigned w = ew[2 * t + 1];
    unsigned nz = __ballot_sync(0xffffffffu, w != 0u);
    __shared__ unsigned s[2];
    if ((t & 31) == 0) s[t >> 5] = nz;
    __syncthreads();
    if (t == 0) g_is64 = ((s[0] | s[1]) == 0u) ? 1 : 0;
}

__device__ __forceinline__ int edge_at(const void* ew, int idx) {
    if (g_is64) return (int)((const long long*)ew)[idx];
    return ((const int*)ew)[idx];
}

// ---------------- CSR construction ----------------
__global__ void zero_deg_k(int n) {
    int i = blockIdx.x * blockDim.x + threadIdx.x;
    if (i < n) {
        g_deg[i] = 0;
        g_as2[i] = 0.f;   // zeroed for gemm2-epilogue atomics
        g_ad2[i] = 0.f;
    }
}

__global__ void count_deg_k(const void* __restrict__ ew, int E, int N) {
    int e = blockIdx.x * blockDim.x + threadIdx.x;
    int ET = E + N;
    if (e >= ET) return;
    int dst = (e < E) ? edge_at(ew, E + e) : (e - E);
    if ((unsigned)dst < (unsigned)N) atomicAdd(&g_deg[dst], 1);
}

__global__ void scanA_k(int n) {
    __shared__ int s[1024];
    int t = threadIdx.x;
    int i = blockIdx.x * 1024 + t;
    int v = (i < n) ? g_deg[i] : 0;
    s[t] = v;
    __syncthreads();
#pragma unroll
    for (int off = 1; off < 1024; off <<= 1) {
        int tmp = (t >= off) ? s[t - off] : 0;
        __syncthreads();
        s[t] += tmp;
        __syncthreads();
    }
    if (i < n) g_off[i] = s[t] - v;
    if (t == 1023) g_bsum[blockIdx.x] = s[1023];
}

__global__ void scanB_k(int nb, int n) {
    int t = threadIdx.x;
    int v = (t < nb) ? g_bsum[t] : 0;
    int lane = t & 31;
    int incl = v;
#pragma unroll
    for (int off = 1; off < 32; off <<= 1) {
        int u = __shfl_up_sync(0xffffffffu, incl, off);
        if (lane >= off) incl += u;
    }
    __shared__ int wt[2];
    if (lane == 31) wt[t >> 5] = incl;
    __syncthreads();
    int add = (t >= 32) ? wt[0] : 0;
    incl += add;
    if (t < nb) g_bsum[t] = incl - v;
    if (t == 63) g_off[n] = incl;
}

__global__ void scanC_k(int n) {
    int t = threadIdx.x;
    int i = blockIdx.x * 1024 + t;
    if (i < n) {
        int o = g_off[i] + g_bsum[blockIdx.x];
        g_off[i] = o;
        g_cur[i] = o;
    }
}

__global__ void fill_csr_k(const void* __restrict__ ew, int E, int N) {
    int e = blockIdx.x * blockDim.x + threadIdx.x;
    int ET = E + N;
    if (e >= ET) return;
    int src, dst;
    if (e < E) { src = edge_at(ew, e); dst = edge_at(ew, E + e); }
    else       { src = e - E; dst = src; }
    if ((unsigned)dst >= (unsigned)N || (unsigned)src >= (unsigned)N) return;
    int pos = atomicAdd(&g_cur[dst], 1);
    g_csr[pos] = src;
}

// ---------------- TF32 tensor-core GEMM, 2-stage cp.async, fused alpha epilogue ----
// BM=128 BN=64 BK=16; 256 threads = 8 warps (4 M x 2 N); warp tile 32x32.
// MODE 1: gemm1 — per-warp head, alpha via shfl-reduce + direct store.
// MODE 2: gemm2 — single head over 64 cols, alpha via shfl-reduce + atomicAdd.
#define GA_PAD 20
#define GB_PAD 72

__device__ __forceinline__ void mma_tf32(float* c, const uint32_t* a, const uint32_t* b) {
    asm volatile(
        "mma.sync.aligned.m16n8k8.row.col.f32.tf32.tf32.f32 "
        "{%0,%1,%2,%3}, {%4,%5,%6,%7}, {%8,%9}, {%0,%1,%2,%3};"
        : "+f"(c[0]), "+f"(c[1]), "+f"(c[2]), "+f"(c[3])
        : "r"(a[0]), "r"(a[1]), "r"(a[2]), "r"(a[3]), "r"(b[0]), "r"(b[1]));
}

__device__ __forceinline__ void cp16(uint32_t smem, const float* gptr, bool valid) {
    int sz = valid ? 16 : 0;
    asm volatile("cp.async.cg.shared.global [%0], [%1], 16, %2;"
                 :: "r"(smem), "l"(gptr), "r"(sz));
}

template <int MODE>
__device__ __forceinline__ void gemm_tf32_body(const float* __restrict__ A,
                                               const float* __restrict__ B,
                                               float* __restrict__ C,
                                               int M, int Nn, int K,
                                               const float* __restrict__ av_src,
                                               const float* __restrict__ av_dst) {
    __shared__ float As[2][128 * GA_PAD];
    __shared__ float Bs[2][16 * GB_PAD];

    int tid = threadIdx.x;
    int wid = tid >> 5, lane = tid & 31;
    int lq = lane >> 2, lr = lane & 3;
    int warp_m = wid & 3, warp_n = wid >> 2;
    int row0 = blockIdx.y * 128, col0 = blockIdx.x * 64;

    uint32_t as_base = (uint32_t)__cvta_generic_to_shared(&As[0][0]);
    uint32_t bs_base = (uint32_t)__cvta_generic_to_shared(&Bs[0][0]);
    const uint32_t as_stage = 128 * GA_PAD * 4;
    const uint32_t bs_stage = 16 * GB_PAD * 4;

    float acc[2][4][4];
#pragma unroll
    for (int i = 0; i < 2; i++)
#pragma unroll
        for (int j = 0; j < 4; j++)
#pragma unroll
            for (int q = 0; q < 4; q++) acc[i][j][q] = 0.f;

    int a_row[2], a_col[2];
#pragma unroll
    for (int u = 0; u < 2; u++) {
        int idx = tid + 256 * u;
        a_row[u] = idx >> 2;
        a_col[u] = (idx & 3) * 4;
    }
    int b_row = tid >> 4, b_col = (tid & 15) * 4;

    int nk = K >> 4;

    auto issue = [&](int kt, int stage) {
#pragma unroll
        for (int u = 0; u < 2; u++) {
            int r = row0 + a_row[u];
            bool v = (r < M);
            const float* gp = A + (long)(v ? r : 0) * K + (kt << 4) + a_col[u];
            cp16(as_base + stage * as_stage + (a_row[u] * GA_PAD + a_col[u]) * 4, gp, v);
        }
        const float* gp = B + (long)((kt << 4) + b_row) * Nn + col0 + b_col;
        cp16(bs_base + stage * bs_stage + (b_row * GB_PAD + b_col) * 4, gp, true);
        asm volatile("cp.async.commit_group;");
    };

    issue(0, 0);

    for (int kt = 0; kt < nk; kt++) {
        int stage = kt & 1;
        if (kt + 1 < nk) {
            issue(kt + 1, stage ^ 1);
            asm volatile("cp.async.wait_group 1;");
        } else {
            asm volatile("cp.async.wait_group 0;");
        }
        __syncthreads();

        const float* Asb = &As[stage][0];
        const float* Bsb = &Bs[stage][0];
#pragma unroll
        for (int kk = 0; kk < 16; kk += 8) {
            uint32_t af[2][4], bf[4][2];
#pragma unroll
            for (int tm = 0; tm < 2; tm++) {
                int bm = warp_m * 32 + tm * 16;
                const float* ap = Asb + kk + lr;
                // raw fp32 bits: tensor core reads the tf32 subset (rz truncation)
                af[tm][0] = __float_as_uint(ap[(bm + lq) * GA_PAD]);
                af[tm][1] = __float_as_uint(ap[(bm + lq + 8) * GA_PAD]);
                af[tm][2] = __float_as_uint(ap[(bm + lq) * GA_PAD + 4]);
                af[tm][3] = __float_as_uint(ap[(bm + lq + 8) * GA_PAD + 4]);
            }
#pragma unroll
            for (int tn = 0; tn < 4; tn++) {
                int bb = warp_n * 32 + tn * 8 + lq;
                bf[tn][0] = __float_as_uint(Bsb[(kk + lr) * GB_PAD + bb]);
                bf[tn][1] = __float_as_uint(Bsb[(kk + lr + 4) * GB_PAD + bb]);
            }
#pragma unroll
            for (int tm = 0; tm < 2; tm++)
#pragma unroll
                for (int tn = 0; tn < 4; tn++)
                    mma_tf32(acc[tm][tn], af[tm], bf[tn]);
        }
        __syncthreads();
    }

    // ---- store C ----
#pragma unroll
    for (int tm = 0; tm < 2; tm++) {
        int r0 = row0 + warp_m * 32 + tm * 16 + lq;
#pragma unroll
        for (int tn = 0; tn < 4; tn++) {
            int c = col0 + warp_n * 32 + tn * 8 + 2 * lr;
            if (r0 < M) {
                float2* p = (float2*)(C + (long)r0 * Nn + c);
                *p = make_float2(acc[tm][tn][0], acc[tm][tn][1]);
            }
            if (r0 + 8 < M) {
                float2* p = (float2*)(C + (long)(r0 + 8) * Nn + c);
                *p = make_float2(acc[tm][tn][2], acc[tm][tn][3]);
            }
        }
    }

    // ---- fused alpha epilogue ----
    // Per thread: partial dot of its 8 columns with a_src/a_dst, per row-half.
    float ps[2][2], pd[2][2];
#pragma unroll
    for (int tm = 0; tm < 2; tm++)
#pragma unroll
        for (int hf = 0; hf < 2; hf++) { ps[tm][hf] = 0.f; pd[tm][hf] = 0.f; }

#pragma unroll
    for (int tn = 0; tn < 4; tn++) {
        int ch = tn * 8 + 2 * lr;   // channel within the warp's 32-col slice
        float s0, s1, d0, d1;
        if (MODE == 1) {
            int head = (col0 >> 5) + warp_n;
            s0 = av_src[head * C1 + ch];     s1 = av_src[head * C1 + ch + 1];
            d0 = av_dst[head * C1 + ch];     d1 = av_dst[head * C1 + ch + 1];
        } else {
            int c = warp_n * 32 + ch;        // single head over 64 cols
            s0 = av_src[c]; s1 = av_src[c + 1];
            d0 = av_dst[c]; d1 = av_dst[c + 1];
        }
#pragma unroll
        for (int tm = 0; tm < 2; tm++) {
            ps[tm][0] = fmaf(s0, acc[tm][tn][0], fmaf(s1, acc[tm][tn][1], ps[tm][0]));
            ps[tm][1] = fmaf(s0, acc[tm][tn][2], fmaf(s1, acc[tm][tn][3], ps[tm][1]));
            pd[tm][0] = fmaf(d0, acc[tm][tn][0], fmaf(d1, acc[tm][tn][1], pd[tm][0]));
            pd[tm][1] = fmaf(d0, acc[tm][tn][2], fmaf(d1, acc[tm][tn][3], pd[tm][1]));
        }
    }
    // reduce over lr (lanes 4*lq + lr; xor 1,2 stay within the group)
#pragma unroll
    for (int tm = 0; tm < 2; tm++)
#pragma unroll
        for (int hf = 0; hf < 2; hf++) {
            ps[tm][hf] += __shfl_xor_sync(0xffffffffu, ps[tm][hf], 1);
            ps[tm][hf] += __shfl_xor_sync(0xffffffffu, ps[tm][hf], 2);
            pd[tm][hf] += __shfl_xor_sync(0xffffffffu, pd[tm][hf], 1);
            pd[tm][hf] += __shfl_xor_sync(0xffffffffu, pd[tm][hf], 2);
        }
    if (lr == 0) {
#pragma unroll
        for (int tm = 0; tm < 2; tm++)
#pragma unroll
            for (int hf = 0; hf < 2; hf++) {
                int r = row0 + warp_m * 32 + tm * 16 + lq + hf * 8;
                if (r < M) {
                    if (MODE == 1) {
                        int head = (col0 >> 5) + warp_n;
                        g_as1[r * H1 + head] = ps[tm][hf];
                        g_ad1[r * H1 + head] = pd[tm][hf];
                    } else {
                        atomicAdd(&g_as2[r], ps[tm][hf]);
                        atomicAdd(&g_ad2[r], pd[tm][hf]);
                    }
                }
            }
    }
}

__global__ void gemm1_k(const float* __restrict__ A, const float* __restrict__ B, int M,
                        const float* __restrict__ av_src, const float* __restrict__ av_dst) {
    gemm_tf32_body<1>(A, B, g_xw1, M, D1, FIN, av_src, av_dst);
}
__global__ void gemm2_k(const float* __restrict__ B, int M,
                        const float* __restrict__ av_src, const float* __restrict__ av_dst) {
    gemm_tf32_body<2>(g_h, B, g_h2, M, OUTC, D1, av_src, av_dst);
}

// ---------------- layer-1 aggregation: one WARP per node ----------------
__global__ void agg1_k(const float* __restrict__ b1, int N) {
    int warp = (blockIdx.x * blockDim.x + threadIdx.x) >> 5;
    if (warp >= N) return;
    int n = warp;
    int lane = threadIdx.x & 31;
    int beg = g_off[n], end = g_off[n + 1];

    float ad = (lane < H1) ? g_ad1[n * H1 + lane] : 0.f;

    float m = -1e30f, denom = 0.f;
    for (int k = beg; k < end; k++) {
        int s = g_csr[k];
        float as = (lane < H1) ? g_as1[s * H1 + lane] : 0.f;
        float e = as + ad;
        e = (e > 0.f) ? e : 0.2f * e;
        if (e > m) {
            denom = denom * __expf(m - e) + 1.f;
            m = e;
        } else {
            denom += __expf(e - m);
        }
    }
    float inv = 1.f / (denom + 1e-16f);

    float acc[H1];
#pragma unroll
    for (int h = 0; h < H1; h++) acc[h] = 0.f;

    for (int k = beg; k < end; k++) {
        int s = g_csr[k];
        float as = (lane < H1) ? g_as1[s * H1 + lane] : 0.f;
        float e = as + ad;
        e = (e > 0.f) ? e : 0.2f * e;
        float w = __expf(e - m) * inv;
        const float* row = g_xw1 + s * D1;
#pragma unroll
        for (int h = 0; h < H1; h++) {
            float wh = __shfl_sync(0xffffffffu, w, h);
            acc[h] = fmaf(wh, row[h * C1 + lane], acc[h]);
        }
    }

#pragma unroll
    for (int h = 0; h < H1; h++) {
        float v = acc[h] + b1[h * C1 + lane];
        v = (v > 0.f) ? v : (__expf(v) - 1.f);
        g_h[n * D1 + h * C1 + lane] = v;
    }
}

// ---------------- layer-2 aggregation + bias + log_softmax ----------------
__global__ void agg2_k(const float* __restrict__ b2, float* __restrict__ out, int N) {
    int warp = (blockIdx.x * blockDim.x + threadIdx.x) >> 5;
    if (warp >= N) return;
    int n = warp;
    int lane = threadIdx.x & 31;
    int beg = g_off[n], end = g_off[n + 1];
    float ad = g_ad2[n];

    float m = -1e30f, denom = 0.f;
    for (int k = beg; k < end; k++) {
        int s = g_csr[k];
        float e = g_as2[s] + ad;
        e = (e > 0.f) ? e : 0.2f * e;
        if (e > m) {
            denom = denom * __expf(m - e) + 1.f;
            m = e;
        } else {
            denom += __expf(e - m);
        }
    }
    float inv = 1.f / (denom + 1e-16f);

    float a0 = 0.f, a1 = 0.f;
    for (int k = beg; k < end; k++) {
        int s = g_csr[k];
        float e = g_as2[s] + ad;
        e = (e > 0.f) ? e : 0.2f * e;
        float w = __expf(e - m) * inv;
        const float* row = g_h2 + s * OUTC;
        a0 = fmaf(w, row[lane], a0);
        a1 = fmaf(w, row[32 + lane], a1);
    }
    a0 += b2[lane];
    a1 += b2[32 + lane];

    float mx = fmaxf(a0, a1);
#pragma unroll
    for (int o = 16; o; o >>= 1) mx = fmaxf(mx, __shfl_xor_sync(0xffffffffu, mx, o));
    float sum = __expf(a0 - mx) + __expf(a1 - mx);
#pragma unroll
    for (int o = 16; o; o >>= 1) sum += __shfl_xor_sync(0xffffffffu, sum, o);
    float lse = mx + __logf(sum);
    out[n * OUTC + lane] = a0 - lse;
    out[n * OUTC + 32 + lane] = a1 - lse;
}

// ---------------- launch ----------------
extern "C" void kernel_launch(void* const* d_in, const int* in_sizes, int n_in,
                              void* d_out, int out_size) {
    const float* x   = (const float*)d_in[0];
    const void*  ei  = d_in[1];
    const float* W1  = (const float*)d_in[2];
    const float* as1 = (const float*)d_in[3];
    const float* ad1 = (const float*)d_in[4];
    const float* b1  = (const float*)d_in[5];
    const float* W2  = (const float*)d_in[6];
    const float* as2 = (const float*)d_in[7];
    const float* ad2 = (const float*)d_in[8];
    const float* b2  = (const float*)d_in[9];
    float* out = (float*)d_out;

    int E = in_sizes[1] / 2;
    int N = in_sizes[0] / FIN;
    int ET = E + N;
    int nb = (N + 1023) / 1024;

    detect_k<<<1, 64>>>((const unsigned*)ei);

    zero_deg_k<<<(N + 255) / 256, 256>>>(N);
    count_deg_k<<<(ET + 255) / 256, 256>>>(ei, E, N);
    scanA_k<<<nb, 1024>>>(N);
    scanB_k<<<1, 64>>>(nb, N);
    scanC_k<<<nb, 1024>>>(N);
    fill_csr_k<<<(ET + 255) / 256, 256>>>(ei, E, N);

    {
        dim3 grid(D1 / 64, (N + 127) / 128);
        gemm1_k<<<grid, 256>>>(x, W1, N, as1, ad1);
    }
    agg1_k<<<(N * 32 + 255) / 256, 256>>>(b1, N);
    {
        dim3 grid(OUTC / 64, (N + 127) / 128);
        gemm2_k<<<grid, 256>>>(W2, N, as2, ad2);
    }
    agg2_k<<<(N * 32 + 255) / 256, 256>>>(b2, out, N);
}

// round 9
// speedup vs baseline: 4.1193x; 1.2421x over previous
#include <cuda_runtime.h>
#include <math.h>
#include <stdint.h>

// ---------------- problem constants (fixed shapes) ----------------
#define MAXN 50000
#define MAXE 800000
#define FIN  512
#define D1   256      // H1 * C1
#define H1   8
#define C1   32
#define OUTC 64

// ---------------- scratch ----------------
__device__ float g_xw1[MAXN * D1];
__device__ float g_h[MAXN * D1];
__device__ float g_h2[MAXN * OUTC];
__device__ float g_as1[MAXN * H1];
__device__ float g_ad1[MAXN * H1];
__device__ float g_as2[MAXN];
__device__ float g_ad2[MAXN];
__device__ float g_w1c[FIN * D1];    // W1 pre-rounded to tf32 (rna)
__device__ float g_w2c[D1 * OUTC];   // W2 pre-rounded to tf32 (rna)
__device__ int   g_deg[MAXN];
__device__ int   g_off[MAXN + 1];
__device__ int   g_cur[MAXN];
__device__ int   g_csr[MAXE + MAXN];
__device__ int   g_bsum[64];
__device__ int   g_is64;

__device__ __forceinline__ uint32_t cvt_tf32(uint32_t x) {
    uint32_t r;
    asm("cvt.rna.tf32.f32 %0, %1;" : "=r"(r) : "f"(__uint_as_float(x)));
    return r;
}

// ---------------- weight pre-conversion (rna) ----------------
__global__ void wconv_k(const float* __restrict__ W1, const float* __restrict__ W2) {
    int i = blockIdx.x * blockDim.x + threadIdx.x;
    int n1 = FIN * D1;
    int tot = n1 + D1 * OUTC;
    for (; i < tot; i += gridDim.x * blockDim.x) {
        if (i < n1) g_w1c[i] = __uint_as_float(cvt_tf32(__float_as_uint(W1[i])));
        else        g_w2c[i - n1] = __uint_as_float(cvt_tf32(__float_as_uint(W2[i - n1])));
    }
}

// ---------------- edge dtype detection ----------------
__global__ void detect_k(const unsigned* __restrict__ ew) {
    int t = threadIdx.x;  // 64 threads
    unsigned w = ew[2 * t + 1];
    unsigned nz = __ballot_sync(0xffffffffu, w != 0u);
    __shared__ unsigned s[2];
    if ((t & 31) == 0) s[t >> 5] = nz;
    __syncthreads();
    if (t == 0) g_is64 = ((s[0] | s[1]) == 0u) ? 1 : 0;
}

__device__ __forceinline__ int edge_at(const void* ew, int idx) {
    if (g_is64) return (int)((const long long*)ew)[idx];
    return ((const int*)ew)[idx];
}

// ---------------- CSR construction ----------------
__global__ void zero_deg_k(int n) {
    int i = blockIdx.x * blockDim.x + threadIdx.x;
    if (i < n) {
        g_deg[i] = 0;
        g_as2[i] = 0.f;
        g_ad2[i] = 0.f;
    }
}

__global__ void count_deg_k(const void* __restrict__ ew, int E, int N) {
    int e = blockIdx.x * blockDim.x + threadIdx.x;
    int ET = E + N;
    if (e >= ET) return;
    int dst = (e < E) ? edge_at(ew, E + e) : (e - E);
    if ((unsigned)dst < (unsigned)N) atomicAdd(&g_deg[dst], 1);
}

__global__ void scanA_k(int n) {
    __shared__ int s[1024];
    int t = threadIdx.x;
    int i = blockIdx.x * 1024 + t;
    int v = (i < n) ? g_deg[i] : 0;
    s[t] = v;
    __syncthreads();
#pragma unroll
    for (int off = 1; off < 1024; off <<= 1) {
        int tmp = (t >= off) ? s[t - off] : 0;
        __syncthreads();
        s[t] += tmp;
        __syncthreads();
    }
    if (i < n) g_off[i] = s[t] - v;
    if (t == 1023) g_bsum[blockIdx.x] = s[1023];
}

__global__ void scanB_k(int nb, int n) {
    int t = threadIdx.x;
    int v = (t < nb) ? g_bsum[t] : 0;
    int lane = t & 31;
    int incl = v;
#pragma unroll
    for (int off = 1; off < 32; off <<= 1) {
        int u = __shfl_up_sync(0xffffffffu, incl, off);
        if (lane >= off) incl += u;
    }
    __shared__ int wt[2];
    if (lane == 31) wt[t >> 5] = incl;
    __syncthreads();
    int add = (t >= 32) ? wt[0] : 0;
    incl += add;
    if (t < nb) g_bsum[t] = incl - v;
    if (t == 63) g_off[n] = incl;
}

__global__ void scanC_k(int n) {
    int t = threadIdx.x;
    int i = blockIdx.x * 1024 + t;
    if (i < n) {
        int o = g_off[i] + g_bsum[blockIdx.x];
        g_off[i] = o;
        g_cur[i] = o;
    }
}

__global__ void fill_csr_k(const void* __restrict__ ew, int E, int N) {
    int e = blockIdx.x * blockDim.x + threadIdx.x;
    int ET = E + N;
    if (e >= ET) return;
    int src, dst;
    if (e < E) { src = edge_at(ew, e); dst = edge_at(ew, E + e); }
    else       { src = e - E; dst = src; }
    if ((unsigned)dst >= (unsigned)N || (unsigned)src >= (unsigned)N) return;
    int pos = atomicAdd(&g_cur[dst], 1);
    g_csr[pos] = src;
}

// ---------------- TF32 tensor-core GEMM, 2-stage cp.async, fused alpha epilogue ----
// B is pre-rounded (raw-bit load); A fragments converted with cvt.rna.
#define GA_PAD 20
#define GB_PAD 72

__device__ __forceinline__ void mma_tf32(float* c, const uint32_t* a, const uint32_t* b) {
    asm volatile(
        "mma.sync.aligned.m16n8k8.row.col.f32.tf32.tf32.f32 "
        "{%0,%1,%2,%3}, {%4,%5,%6,%7}, {%8,%9}, {%0,%1,%2,%3};"
        : "+f"(c[0]), "+f"(c[1]), "+f"(c[2]), "+f"(c[3])
        : "r"(a[0]), "r"(a[1]), "r"(a[2]), "r"(a[3]), "r"(b[0]), "r"(b[1]));
}

__device__ __forceinline__ void cp16(uint32_t smem, const float* gptr, bool valid) {
    int sz = valid ? 16 : 0;
    asm volatile("cp.async.cg.shared.global [%0], [%1], 16, %2;"
                 :: "r"(smem), "l"(gptr), "r"(sz));
}

template <int MODE>
__device__ __forceinline__ void gemm_tf32_body(const float* __restrict__ A,
                                               const float* __restrict__ B,
                                               float* __restrict__ C,
                                               int M, int Nn, int K,
                                               const float* __restrict__ av_src,
                                               const float* __restrict__ av_dst) {
    __shared__ float As[2][128 * GA_PAD];
    __shared__ float Bs[2][16 * GB_PAD];

    int tid = threadIdx.x;
    int wid = tid >> 5, lane = tid & 31;
    int lq = lane >> 2, lr = lane & 3;
    int warp_m = wid & 3, warp_n = wid >> 2;
    int row0 = blockIdx.y * 128, col0 = blockIdx.x * 64;

    uint32_t as_base = (uint32_t)__cvta_generic_to_shared(&As[0][0]);
    uint32_t bs_base = (uint32_t)__cvta_generic_to_shared(&Bs[0][0]);
    const uint32_t as_stage = 128 * GA_PAD * 4;
    const uint32_t bs_stage = 16 * GB_PAD * 4;

    float acc[2][4][4];
#pragma unroll
    for (int i = 0; i < 2; i++)
#pragma unroll
        for (int j = 0; j < 4; j++)
#pragma unroll
            for (int q = 0; q < 4; q++) acc[i][j][q] = 0.f;

    int a_row[2], a_col[2];
#pragma unroll
    for (int u = 0; u < 2; u++) {
        int idx = tid + 256 * u;
        a_row[u] = idx >> 2;
        a_col[u] = (idx & 3) * 4;
    }
    int b_row = tid >> 4, b_col = (tid & 15) * 4;

    int nk = K >> 4;

    auto issue = [&](int kt, int stage) {
#pragma unroll
        for (int u = 0; u < 2; u++) {
            int r = row0 + a_row[u];
            bool v = (r < M);
            const float* gp = A + (long)(v ? r : 0) * K + (kt << 4) + a_col[u];
            cp16(as_base + stage * as_stage + (a_row[u] * GA_PAD + a_col[u]) * 4, gp, v);
        }
        const float* gp = B + (long)((kt << 4) + b_row) * Nn + col0 + b_col;
        cp16(bs_base + stage * bs_stage + (b_row * GB_PAD + b_col) * 4, gp, true);
        asm volatile("cp.async.commit_group;");
    };

    issue(0, 0);

    for (int kt = 0; kt < nk; kt++) {
        int stage = kt & 1;
        if (kt + 1 < nk) {
            issue(kt + 1, stage ^ 1);
            asm volatile("cp.async.wait_group 1;");
        } else {
            asm volatile("cp.async.wait_group 0;");
        }
        __syncthreads();

        const float* Asb = &As[stage][0];
        const float* Bsb = &Bs[stage][0];
#pragma unroll
        for (int kk = 0; kk < 16; kk += 8) {
            uint32_t af[2][4], bf[4][2];
#pragma unroll
            for (int tm = 0; tm < 2; tm++) {
                int bm = warp_m * 32 + tm * 16;
                const float* ap = Asb + kk + lr;
                af[tm][0] = cvt_tf32(__float_as_uint(ap[(bm + lq) * GA_PAD]));
                af[tm][1] = cvt_tf32(__float_as_uint(ap[(bm + lq + 8) * GA_PAD]));
                af[tm][2] = cvt_tf32(__float_as_uint(ap[(bm + lq) * GA_PAD + 4]));
                af[tm][3] = cvt_tf32(__float_as_uint(ap[(bm + lq + 8) * GA_PAD + 4]));
            }
#pragma unroll
            for (int tn = 0; tn < 4; tn++) {
                int bb = warp_n * 32 + tn * 8 + lq;
                bf[tn][0] = __float_as_uint(Bsb[(kk + lr) * GB_PAD + bb]);       // pre-rounded
                bf[tn][1] = __float_as_uint(Bsb[(kk + lr + 4) * GB_PAD + bb]);
            }
#pragma unroll
            for (int tm = 0; tm < 2; tm++)
#pragma unroll
                for (int tn = 0; tn < 4; tn++)
                    mma_tf32(acc[tm][tn], af[tm], bf[tn]);
        }
        __syncthreads();
    }

    // ---- store C ----
#pragma unroll
    for (int tm = 0; tm < 2; tm++) {
        int r0 = row0 + warp_m * 32 + tm * 16 + lq;
#pragma unroll
        for (int tn = 0; tn < 4; tn++) {
            int c = col0 + warp_n * 32 + tn * 8 + 2 * lr;
            if (r0 < M) {
                float2* p = (float2*)(C + (long)r0 * Nn + c);
                *p = make_float2(acc[tm][tn][0], acc[tm][tn][1]);
            }
            if (r0 + 8 < M) {
                float2* p = (float2*)(C + (long)(r0 + 8) * Nn + c);
                *p = make_float2(acc[tm][tn][2], acc[tm][tn][3]);
            }
        }
    }

    // ---- fused alpha epilogue ----
    float ps[2][2], pd[2][2];
#pragma unroll
    for (int tm = 0; tm < 2; tm++)
#pragma unroll
        for (int hf = 0; hf < 2; hf++) { ps[tm][hf] = 0.f; pd[tm][hf] = 0.f; }

#pragma unroll
    for (int tn = 0; tn < 4; tn++) {
        int ch = tn * 8 + 2 * lr;
        float s0, s1, d0, d1;
        if (MODE == 1) {
            int head = (col0 >> 5) + warp_n;
            s0 = av_src[head * C1 + ch];     s1 = av_src[head * C1 + ch + 1];
            d0 = av_dst[head * C1 + ch];     d1 = av_dst[head * C1 + ch + 1];
        } else {
            int c = warp_n * 32 + ch;
            s0 = av_src[c]; s1 = av_src[c + 1];
            d0 = av_dst[c]; d1 = av_dst[c + 1];
        }
#pragma unroll
        for (int tm = 0; tm < 2; tm++) {
            ps[tm][0] = fmaf(s0, acc[tm][tn][0], fmaf(s1, acc[tm][tn][1], ps[tm][0]));
            ps[tm][1] = fmaf(s0, acc[tm][tn][2], fmaf(s1, acc[tm][tn][3], ps[tm][1]));
            pd[tm][0] = fmaf(d0, acc[tm][tn][0], fmaf(d1, acc[tm][tn][1], pd[tm][0]));
            pd[tm][1] = fmaf(d0, acc[tm][tn][2], fmaf(d1, acc[tm][tn][3], pd[tm][1]));
        }
    }
#pragma unroll
    for (int tm = 0; tm < 2; tm++)
#pragma unroll
        for (int hf = 0; hf < 2; hf++) {
            ps[tm][hf] += __shfl_xor_sync(0xffffffffu, ps[tm][hf], 1);
            ps[tm][hf] += __shfl_xor_sync(0xffffffffu, ps[tm][hf], 2);
            pd[tm][hf] += __shfl_xor_sync(0xffffffffu, pd[tm][hf], 1);
            pd[tm][hf] += __shfl_xor_sync(0xffffffffu, pd[tm][hf], 2);
        }
    if (lr == 0) {
#pragma unroll
        for (int tm = 0; tm < 2; tm++)
#pragma unroll
            for (int hf = 0; hf < 2; hf++) {
                int r = row0 + warp_m * 32 + tm * 16 + lq + hf * 8;
                if (r < M) {
                    if (MODE == 1) {
                        int head = (col0 >> 5) + warp_n;
                        g_as1[r * H1 + head] = ps[tm][hf];
                        g_ad1[r * H1 + head] = pd[tm][hf];
                    } else {
                        atomicAdd(&g_as2[r], ps[tm][hf]);
                        atomicAdd(&g_ad2[r], pd[tm][hf]);
                    }
                }
            }
    }
}

__global__ void gemm1_k(const float* __restrict__ A, int M,
                        const float* __restrict__ av_src, const float* __restrict__ av_dst) {
    gemm_tf32_body<1>(A, g_w1c, g_xw1, M, D1, FIN, av_src, av_dst);
}
__global__ void gemm2_k(int M,
                        const float* __restrict__ av_src, const float* __restrict__ av_dst) {
    gemm_tf32_body<2>(g_h, g_w2c, g_h2, M, OUTC, D1, av_src, av_dst);
}

// ---------------- layer-1 aggregation: one WARP per node, SINGLE pass ----------------
// Unnormalized softmax: |e| <~ 25 from data scale, exp safe in fp32.
__global__ void agg1_k(const float* __restrict__ b1, int N) {
    int warp = (blockIdx.x * blockDim.x + threadIdx.x) >> 5;
    if (warp >= N) return;
    int n = warp;
    int lane = threadIdx.x & 31;
    int beg = g_off[n], end = g_off[n + 1];

    float ad = (lane < H1) ? g_ad1[n * H1 + lane] : 0.f;

    float denom = 0.f;
    float acc[H1];
#pragma unroll
    for (int h = 0; h < H1; h++) acc[h] = 0.f;

    for (int k = beg; k < end; k++) {
        int s = g_csr[k];
        float as = (lane < H1) ? g_as1[s * H1 + lane] : 0.f;
        float e = as + ad;
        e = (e > 0.f) ? e : 0.2f * e;
        float w = __expf(e);            // lanes 0..7 hold per-head weight
        denom += w;
        const float* row = g_xw1 + s * D1;
#pragma unroll
        for (int h = 0; h < H1; h++) {
            float wh = __shfl_sync(0xffffffffu, w, h);
            acc[h] = fmaf(wh, row[h * C1 + lane], acc[h]);
        }
    }
    float inv = 1.f / (denom + 1e-16f);  // per-head in lanes 0..7

#pragma unroll
    for (int h = 0; h < H1; h++) {
        float invh = __shfl_sync(0xffffffffu, inv, h);
        float v = acc[h] * invh + b1[h * C1 + lane];
        v = (v > 0.f) ? v : (__expf(v) - 1.f);
        g_h[n * D1 + h * C1 + lane] = v;
    }
}

// ---------------- layer-2 aggregation + bias + log_softmax: SINGLE pass ----------------
__global__ void agg2_k(const float* __restrict__ b2, float* __restrict__ out, int N) {
    int warp = (blockIdx.x * blockDim.x + threadIdx.x) >> 5;
    if (warp >= N) return;
    int n = warp;
    int lane = threadIdx.x & 31;
    int beg = g_off[n], end = g_off[n + 1];
    float ad = g_ad2[n];

    float denom = 0.f, a0 = 0.f, a1 = 0.f;
    for (int k = beg; k < end; k++) {
        int s = g_csr[k];
        float e = g_as2[s] + ad;
        e = (e > 0.f) ? e : 0.2f * e;
        float w = __expf(e);
        denom += w;
        const float* row = g_h2 + s * OUTC;
        a0 = fmaf(w, row[lane], a0);
        a1 = fmaf(w, row[32 + lane], a1);
    }
    float inv = 1.f / (denom + 1e-16f);
    a0 = a0 * inv + b2[lane];
    a1 = a1 * inv + b2[32 + lane];

    float mx = fmaxf(a0, a1);
#pragma unroll
    for (int o = 16; o; o >>= 1) mx = fmaxf(mx, __shfl_xor_sync(0xffffffffu, mx, o));
    float sum = __expf(a0 - mx) + __expf(a1 - mx);
#pragma unroll
    for (int o = 16; o; o >>= 1) sum += __shfl_xor_sync(0xffffffffu, sum, o);
    float lse = mx + __logf(sum);
    out[n * OUTC + lane] = a0 - lse;
    out[n * OUTC + 32 + lane] = a1 - lse;
}

// ---------------- launch ----------------
extern "C" void kernel_launch(void* const* d_in, const int* in_sizes, int n_in,
                              void* d_out, int out_size) {
    const float* x   = (const float*)d_in[0];
    const void*  ei  = d_in[1];
    const float* W1  = (const float*)d_in[2];
    const float* as1 = (const float*)d_in[3];
    const float* ad1 = (const float*)d_in[4];
    const float* b1  = (const float*)d_in[5];
    const float* W2  = (const float*)d_in[6];
    const float* as2 = (const float*)d_in[7];
    const float* ad2 = (const float*)d_in[8];
    const float* b2  = (const float*)d_in[9];
    float* out = (float*)d_out;

    int E = in_sizes[1] / 2;
    int N = in_sizes[0] / FIN;
    int ET = E + N;
    int nb = (N + 1023) / 1024;

    detect_k<<<1, 64>>>((const unsigned*)ei);
    wconv_k<<<160, 256>>>(W1, W2);

    zero_deg_k<<<(N + 255) / 256, 256>>>(N);
    count_deg_k<<<(ET + 255) / 256, 256>>>(ei, E, N);
    scanA_k<<<nb, 1024>>>(N);
    scanB_k<<<1, 64>>>(nb, N);
    scanC_k<<<nb, 1024>>>(N);
    fill_csr_k<<<(ET + 255) / 256, 256>>>(ei, E, N);

    {
        dim3 grid(D1 / 64, (N + 127) / 128);
        gemm1_k<<<grid, 256>>>(x, N, as1, ad1);
    }
    agg1_k<<<(N * 32 + 255) / 256, 256>>>(b1, N);
    {
        dim3 grid(OUTC / 64, (N + 127) / 128);
        gemm2_k<<<grid, 256>>>(N, as2, ad2);
    }
    agg2_k<<<(N * 32 + 255) / 256, 256>>>(b2, out, N);
}

// round 10
// speedup vs baseline: 4.3890x; 1.0655x over previous
#include <cuda_runtime.h>
#include <math.h>
#include <stdint.h>

// ---------------- problem constants (fixed shapes) ----------------
#define MAXN 50000
#define MAXE 800000
#define FIN  512
#define D1   256      // H1 * C1
#define H1   8
#define C1   32
#define OUTC 64

// ---------------- scratch ----------------
__device__ float g_xw1[MAXN * D1];
__device__ float g_h[MAXN * D1];
__device__ float g_h2[MAXN * OUTC];
__device__ float g_as1[MAXN * H1];
__device__ float g_ad1[MAXN * H1];
__device__ float g_as2[MAXN];
__device__ float g_ad2[MAXN];
__device__ float g_w1c[FIN * D1];    // W1 pre-rounded to tf32 (rna)
__device__ float g_w2c[D1 * OUTC];   // W2 pre-rounded to tf32 (rna)
__device__ int   g_deg[MAXN];
__device__ int   g_off[MAXN + 1];
__device__ int   g_cur[MAXN];
__device__ int   g_csr[MAXE + MAXN];
__device__ int   g_bsum[64];
__device__ int   g_is64;

__device__ __forceinline__ uint32_t cvt_tf32(uint32_t x) {
    uint32_t r;
    asm("cvt.rna.tf32.f32 %0, %1;" : "=r"(r) : "f"(__uint_as_float(x)));
    return r;
}

// ---------------- weight pre-conversion (rna) ----------------
__global__ void wconv_k(const float* __restrict__ W1, const float* __restrict__ W2) {
    int i = blockIdx.x * blockDim.x + threadIdx.x;
    int n1 = FIN * D1;
    int tot = n1 + D1 * OUTC;
    for (; i < tot; i += gridDim.x * blockDim.x) {
        if (i < n1) g_w1c[i] = __uint_as_float(cvt_tf32(__float_as_uint(W1[i])));
        else        g_w2c[i - n1] = __uint_as_float(cvt_tf32(__float_as_uint(W2[i - n1])));
    }
}

// ---------------- edge dtype detection ----------------
__global__ void detect_k(const unsigned* __restrict__ ew) {
    int t = threadIdx.x;  // 64 threads
    unsigned w = ew[2 * t + 1];
    unsigned nz = __ballot_sync(0xffffffffu, w != 0u);
    __shared__ unsigned s[2];
    if ((t & 31) == 0) s[t >> 5] = nz;
    __syncthreads();
    if (t == 0) g_is64 = ((s[0] | s[1]) == 0u) ? 1 : 0;
}

__device__ __forceinline__ int edge_at(const void* ew, int idx) {
    if (g_is64) return (int)((const long long*)ew)[idx];
    return ((const int*)ew)[idx];
}

// ---------------- CSR construction ----------------
__global__ void zero_deg_k(int n) {
    int i = blockIdx.x * blockDim.x + threadIdx.x;
    if (i < n) {
        g_deg[i] = 0;
        g_as2[i] = 0.f;
        g_ad2[i] = 0.f;
    }
}

__global__ void count_deg_k(const void* __restrict__ ew, int E, int N) {
    int e = blockIdx.x * blockDim.x + threadIdx.x;
    int ET = E + N;
    if (e >= ET) return;
    int dst = (e < E) ? edge_at(ew, E + e) : (e - E);
    if ((unsigned)dst < (unsigned)N) atomicAdd(&g_deg[dst], 1);
}

__global__ void scanA_k(int n) {
    __shared__ int s[1024];
    int t = threadIdx.x;
    int i = blockIdx.x * 1024 + t;
    int v = (i < n) ? g_deg[i] : 0;
    s[t] = v;
    __syncthreads();
#pragma unroll
    for (int off = 1; off < 1024; off <<= 1) {
        int tmp = (t >= off) ? s[t - off] : 0;
        __syncthreads();
        s[t] += tmp;
        __syncthreads();
    }
    if (i < n) g_off[i] = s[t] - v;
    if (t == 1023) g_bsum[blockIdx.x] = s[1023];
}

__global__ void scanB_k(int nb, int n) {
    int t = threadIdx.x;
    int v = (t < nb) ? g_bsum[t] : 0;
    int lane = t & 31;
    int incl = v;
#pragma unroll
    for (int off = 1; off < 32; off <<= 1) {
        int u = __shfl_up_sync(0xffffffffu, incl, off);
        if (lane >= off) incl += u;
    }
    __shared__ int wt[2];
    if (lane == 31) wt[t >> 5] = incl;
    __syncthreads();
    int add = (t >= 32) ? wt[0] : 0;
    incl += add;
    if (t < nb) g_bsum[t] = incl - v;
    if (t == 63) g_off[n] = incl;
}

__global__ void scanC_k(int n) {
    int t = threadIdx.x;
    int i = blockIdx.x * 1024 + t;
    if (i < n) {
        int o = g_off[i] + g_bsum[blockIdx.x];
        g_off[i] = o;
        g_cur[i] = o;
    }
}

__global__ void fill_csr_k(const void* __restrict__ ew, int E, int N) {
    int e = blockIdx.x * blockDim.x + threadIdx.x;
    int ET = E + N;
    if (e >= ET) return;
    int src, dst;
    if (e < E) { src = edge_at(ew, e); dst = edge_at(ew, E + e); }
    else       { src = e - E; dst = src; }
    if ((unsigned)dst >= (unsigned)N || (unsigned)src >= (unsigned)N) return;
    int pos = atomicAdd(&g_cur[dst], 1);
    g_csr[pos] = src;
}

// ---------------- TF32 tensor-core GEMM, 2-stage cp.async, fused alpha epilogue ----
#define GA_PAD 20
#define GB_PAD 72

__device__ __forceinline__ void mma_tf32(float* c, const uint32_t* a, const uint32_t* b) {
    asm volatile(
        "mma.sync.aligned.m16n8k8.row.col.f32.tf32.tf32.f32 "
        "{%0,%1,%2,%3}, {%4,%5,%6,%7}, {%8,%9}, {%0,%1,%2,%3};"
        : "+f"(c[0]), "+f"(c[1]), "+f"(c[2]), "+f"(c[3])
        : "r"(a[0]), "r"(a[1]), "r"(a[2]), "r"(a[3]), "r"(b[0]), "r"(b[1]));
}

__device__ __forceinline__ void cp16(uint32_t smem, const float* gptr, bool valid) {
    int sz = valid ? 16 : 0;
    asm volatile("cp.async.cg.shared.global [%0], [%1], 16, %2;"
                 :: "r"(smem), "l"(gptr), "r"(sz));
}

template <int MODE>
__device__ __forceinline__ void gemm_tf32_body(const float* __restrict__ A,
                                               const float* __restrict__ B,
                                               float* __restrict__ C,
                                               int M, int Nn, int K,
                                               const float* __restrict__ av_src,
                                               const float* __restrict__ av_dst) {
    __shared__ float As[2][128 * GA_PAD];
    __shared__ float Bs[2][16 * GB_PAD];

    int tid = threadIdx.x;
    int wid = tid >> 5, lane = tid & 31;
    int lq = lane >> 2, lr = lane & 3;
    int warp_m = wid & 3, warp_n = wid >> 2;
    int row0 = blockIdx.y * 128, col0 = blockIdx.x * 64;

    uint32_t as_base = (uint32_t)__cvta_generic_to_shared(&As[0][0]);
    uint32_t bs_base = (uint32_t)__cvta_generic_to_shared(&Bs[0][0]);
    const uint32_t as_stage = 128 * GA_PAD * 4;
    const uint32_t bs_stage = 16 * GB_PAD * 4;

    float acc[2][4][4];
#pragma unroll
    for (int i = 0; i < 2; i++)
#pragma unroll
        for (int j = 0; j < 4; j++)
#pragma unroll
            for (int q = 0; q < 4; q++) acc[i][j][q] = 0.f;

    int a_row[2], a_col[2];
#pragma unroll
    for (int u = 0; u < 2; u++) {
        int idx = tid + 256 * u;
        a_row[u] = idx >> 2;
        a_col[u] = (idx & 3) * 4;
    }
    int b_row = tid >> 4, b_col = (tid & 15) * 4;

    int nk = K >> 4;

    auto issue = [&](int kt, int stage) {
#pragma unroll
        for (int u = 0; u < 2; u++) {
            int r = row0 + a_row[u];
            bool v = (r < M);
            const float* gp = A + (long)(v ? r : 0) * K + (kt << 4) + a_col[u];
            cp16(as_base + stage * as_stage + (a_row[u] * GA_PAD + a_col[u]) * 4, gp, v);
        }
        const float* gp = B + (long)((kt << 4) + b_row) * Nn + col0 + b_col;
        cp16(bs_base + stage * bs_stage + (b_row * GB_PAD + b_col) * 4, gp, true);
        asm volatile("cp.async.commit_group;");
    };

    issue(0, 0);

    for (int kt = 0; kt < nk; kt++) {
        int stage = kt & 1;
        if (kt + 1 < nk) {
            issue(kt + 1, stage ^ 1);
            asm volatile("cp.async.wait_group 1;");
        } else {
            asm volatile("cp.async.wait_group 0;");
        }
        __syncthreads();

        const float* Asb = &As[stage][0];
        const float* Bsb = &Bs[stage][0];
#pragma unroll
        for (int kk = 0; kk < 16; kk += 8) {
            uint32_t af[2][4], bf[4][2];
#pragma unroll
            for (int tm = 0; tm < 2; tm++) {
                int bm = warp_m * 32 + tm * 16;
                const float* ap = Asb + kk + lr;
                af[tm][0] = cvt_tf32(__float_as_uint(ap[(bm + lq) * GA_PAD]));
                af[tm][1] = cvt_tf32(__float_as_uint(ap[(bm + lq + 8) * GA_PAD]));
                af[tm][2] = cvt_tf32(__float_as_uint(ap[(bm + lq) * GA_PAD + 4]));
                af[tm][3] = cvt_tf32(__float_as_uint(ap[(bm + lq + 8) * GA_PAD + 4]));
            }
#pragma unroll
            for (int tn = 0; tn < 4; tn++) {
                int bb = warp_n * 32 + tn * 8 + lq;
                bf[tn][0] = __float_as_uint(Bsb[(kk + lr) * GB_PAD + bb]);
                bf[tn][1] = __float_as_uint(Bsb[(kk + lr + 4) * GB_PAD + bb]);
            }
#pragma unroll
            for (int tm = 0; tm < 2; tm++)
#pragma unroll
                for (int tn = 0; tn < 4; tn++)
                    mma_tf32(acc[tm][tn], af[tm], bf[tn]);
        }
        __syncthreads();
    }

    // ---- store C ----
#pragma unroll
    for (int tm = 0; tm < 2; tm++) {
        int r0 = row0 + warp_m * 32 + tm * 16 + lq;
#pragma unroll
        for (int tn = 0; tn < 4; tn++) {
            int c = col0 + warp_n * 32 + tn * 8 + 2 * lr;
            if (r0 < M) {
                float2* p = (float2*)(C + (long)r0 * Nn + c);
                *p = make_float2(acc[tm][tn][0], acc[tm][tn][1]);
            }
            if (r0 + 8 < M) {
                float2* p = (float2*)(C + (long)(r0 + 8) * Nn + c);
                *p = make_float2(acc[tm][tn][2], acc[tm][tn][3]);
            }
        }
    }

    // ---- fused alpha epilogue ----
    float ps[2][2], pd[2][2];
#pragma unroll
    for (int tm = 0; tm < 2; tm++)
#pragma unroll
        for (int hf = 0; hf < 2; hf++) { ps[tm][hf] = 0.f; pd[tm][hf] = 0.f; }

#pragma unroll
    for (int tn = 0; tn < 4; tn++) {
        int ch = tn * 8 + 2 * lr;
        float s0, s1, d0, d1;
        if (MODE == 1) {
            int head = (col0 >> 5) + warp_n;
            s0 = av_src[head * C1 + ch];     s1 = av_src[head * C1 + ch + 1];
            d0 = av_dst[head * C1 + ch];     d1 = av_dst[head * C1 + ch + 1];
        } else {
            int c = warp_n * 32 + ch;
            s0 = av_src[c]; s1 = av_src[c + 1];
            d0 = av_dst[c]; d1 = av_dst[c + 1];
        }
#pragma unroll
        for (int tm = 0; tm < 2; tm++) {
            ps[tm][0] = fmaf(s0, acc[tm][tn][0], fmaf(s1, acc[tm][tn][1], ps[tm][0]));
            ps[tm][1] = fmaf(s0, acc[tm][tn][2], fmaf(s1, acc[tm][tn][3], ps[tm][1]));
            pd[tm][0] = fmaf(d0, acc[tm][tn][0], fmaf(d1, acc[tm][tn][1], pd[tm][0]));
            pd[tm][1] = fmaf(d0, acc[tm][tn][2], fmaf(d1, acc[tm][tn][3], pd[tm][1]));
        }
    }
#pragma unroll
    for (int tm = 0; tm < 2; tm++)
#pragma unroll
        for (int hf = 0; hf < 2; hf++) {
            ps[tm][hf] += __shfl_xor_sync(0xffffffffu, ps[tm][hf], 1);
            ps[tm][hf] += __shfl_xor_sync(0xffffffffu, ps[tm][hf], 2);
            pd[tm][hf] += __shfl_xor_sync(0xffffffffu, pd[tm][hf], 1);
            pd[tm][hf] += __shfl_xor_sync(0xffffffffu, pd[tm][hf], 2);
        }
    if (lr == 0) {
#pragma unroll
        for (int tm = 0; tm < 2; tm++)
#pragma unroll
            for (int hf = 0; hf < 2; hf++) {
                int r = row0 + warp_m * 32 + tm * 16 + lq + hf * 8;
                if (r < M) {
                    if (MODE == 1) {
                        int head = (col0 >> 5) + warp_n;
                        g_as1[r * H1 + head] = ps[tm][hf];
                        g_ad1[r * H1 + head] = pd[tm][hf];
                    } else {
                        atomicAdd(&g_as2[r], ps[tm][hf]);
                        atomicAdd(&g_ad2[r], pd[tm][hf]);
                    }
                }
            }
    }
}

__global__ void gemm1_k(const float* __restrict__ A, int M,
                        const float* __restrict__ av_src, const float* __restrict__ av_dst) {
    gemm_tf32_body<1>(A, g_w1c, g_xw1, M, D1, FIN, av_src, av_dst);
}
__global__ void gemm2_k(int M,
                        const float* __restrict__ av_src, const float* __restrict__ av_dst) {
    gemm_tf32_body<2>(g_h, g_w2c, g_h2, M, OUTC, D1, av_src, av_dst);
}

// ---------------- layer-1 aggregation: one WARP per node, SINGLE pass ----------------
__global__ void agg1_k(const float* __restrict__ b1, int N) {
    int warp = (blockIdx.x * blockDim.x + threadIdx.x) >> 5;
    if (warp >= N) return;
    int n = warp;
    int lane = threadIdx.x & 31;
    int beg = g_off[n], end = g_off[n + 1];

    float ad = (lane < H1) ? g_ad1[n * H1 + lane] : 0.f;

    float denom = 0.f;
    float acc[H1];
#pragma unroll
    for (int h = 0; h < H1; h++) acc[h] = 0.f;

    for (int k = beg; k < end; k++) {
        int s = g_csr[k];
        float as = (lane < H1) ? g_as1[s * H1 + lane] : 0.f;
        float e = as + ad;
        e = (e > 0.f) ? e : 0.2f * e;
        float w = __expf(e);
        denom += w;
        const float* row = g_xw1 + s * D1;
#pragma unroll
        for (int h = 0; h < H1; h++) {
            float wh = __shfl_sync(0xffffffffu, w, h);
            acc[h] = fmaf(wh, row[h * C1 + lane], acc[h]);
        }
    }
    float inv = 1.f / (denom + 1e-16f);

#pragma unroll
    for (int h = 0; h < H1; h++) {
        float invh = __shfl_sync(0xffffffffu, inv, h);
        float v = acc[h] * invh + b1[h * C1 + lane];
        v = (v > 0.f) ? v : (__expf(v) - 1.f);
        g_h[n * D1 + h * C1 + lane] = v;
    }
}

// ---------------- layer-2 aggregation + bias + log_softmax: SINGLE pass ----------------
__global__ void agg2_k(const float* __restrict__ b2, float* __restrict__ out, int N) {
    int warp = (blockIdx.x * blockDim.x + threadIdx.x) >> 5;
    if (warp >= N) return;
    int n = warp;
    int lane = threadIdx.x & 31;
    int beg = g_off[n], end = g_off[n + 1];
    float ad = g_ad2[n];

    float denom = 0.f, a0 = 0.f, a1 = 0.f;
    for (int k = beg; k < end; k++) {
        int s = g_csr[k];
        float e = g_as2[s] + ad;
        e = (e > 0.f) ? e : 0.2f * e;
        float w = __expf(e);
        denom += w;
        const float* row = g_h2 + s * OUTC;
        a0 = fmaf(w, row[lane], a0);
        a1 = fmaf(w, row[32 + lane], a1);
    }
    float inv = 1.f / (denom + 1e-16f);
    a0 = a0 * inv + b2[lane];
    a1 = a1 * inv + b2[32 + lane];

    float mx = fmaxf(a0, a1);
#pragma unroll
    for (int o = 16; o; o >>= 1) mx = fmaxf(mx, __shfl_xor_sync(0xffffffffu, mx, o));
    float sum = __expf(a0 - mx) + __expf(a1 - mx);
#pragma unroll
    for (int o = 16; o; o >>= 1) sum += __shfl_xor_sync(0xffffffffu, sum, o);
    float lse = mx + __logf(sum);
    out[n * OUTC + lane] = a0 - lse;
    out[n * OUTC + 32 + lane] = a1 - lse;
}

// ---------------- launch ----------------
extern "C" void kernel_launch(void* const* d_in, const int* in_sizes, int n_in,
                              void* d_out, int out_size) {
    const float* x   = (const float*)d_in[0];
    const void*  ei  = d_in[1];
    const float* W1  = (const float*)d_in[2];
    const float* as1 = (const float*)d_in[3];
    const float* ad1 = (const float*)d_in[4];
    const float* b1  = (const float*)d_in[5];
    const float* W2  = (const float*)d_in[6];
    const float* as2 = (const float*)d_in[7];
    const float* ad2 = (const float*)d_in[8];
    const float* b2  = (const float*)d_in[9];
    float* out = (float*)d_out;

    int E = in_sizes[1] / 2;
    int N = in_sizes[0] / FIN;
    int ET = E + N;
    int nb = (N + 1023) / 1024;

    // Fork a second stream so the CSR chain overlaps wconv+gemm1 in the graph.
    cudaStream_t s2;
    cudaStreamCreateWithFlags(&s2, cudaStreamNonBlocking);
    cudaEvent_t eFork, eJoin;
    cudaEventCreateWithFlags(&eFork, cudaEventDisableTiming);
    cudaEventCreateWithFlags(&eJoin, cudaEventDisableTiming);

    cudaEventRecord(eFork, 0);          // legacy default stream (capture origin)
    cudaStreamWaitEvent(s2, eFork, 0);

    // --- branch A (s2): CSR construction ---
    detect_k<<<1, 64, 0, s2>>>((const unsigned*)ei);
    zero_deg_k<<<(N + 255) / 256, 256, 0, s2>>>(N);
    count_deg_k<<<(ET + 255) / 256, 256, 0, s2>>>(ei, E, N);
    scanA_k<<<nb, 1024, 0, s2>>>(N);
    scanB_k<<<1, 64, 0, s2>>>(nb, N);
    scanC_k<<<nb, 1024, 0, s2>>>(N);
    fill_csr_k<<<(ET + 255) / 256, 256, 0, s2>>>(ei, E, N);
    cudaEventRecord(eJoin, s2);

    // --- branch B (default stream): weights + GEMM1 + fused alpha1 ---
    wconv_k<<<160, 256>>>(W1, W2);
    {
        dim3 grid(D1 / 64, (N + 127) / 128);
        gemm1_k<<<grid, 256>>>(x, N, as1, ad1);
    }

    // join: aggregation needs CSR + alphas
    cudaStreamWaitEvent(0, eJoin, 0);

    agg1_k<<<(N * 32 + 255) / 256, 256>>>(b1, N);
    {
        dim3 grid(OUTC / 64, (N + 127) / 128);
        gemm2_k<<<grid, 256>>>(N, as2, ad2);
    }
    agg2_k<<<(N * 32 + 255) / 256, 256>>>(b2, out, N);

    cudaEventDestroy(eFork);
    cudaEventDestroy(eJoin);
    cudaStreamDestroy(s2);
}

// round 11
// speedup vs baseline: 4.4152x; 1.0060x over previous
#include <cuda_runtime.h>
#include <cuda_fp16.h>
#include <math.h>
#include <stdint.h>

// ---------------- problem constants (fixed shapes) ----------------
#define MAXN 50000
#define MAXE 800000
#define FIN  512
#define D1   256      // H1 * C1
#define H1   8
#define C1   32
#define OUTC 64

// ---------------- scratch ----------------
__device__ __half g_xw1h[MAXN * D1];   // layer1 linear output, fp16 (gather format)
__device__ float  g_h[MAXN * D1];      // layer1 activation (fp32, gemm2 input)
__device__ __half g_h2h[MAXN * OUTC];  // layer2 linear output, fp16 (gather format)
__device__ float  g_as1[MAXN * H1];
__device__ float  g_ad1[MAXN * H1];
__device__ float  g_as2[MAXN];
__device__ float  g_ad2[MAXN];
__device__ float  g_w1c[FIN * D1];     // W1 pre-rounded to tf32 (rna)
__device__ float  g_w2c[D1 * OUTC];    // W2 pre-rounded to tf32 (rna)
__device__ int    g_deg[MAXN];
__device__ int    g_off[MAXN + 1];
__device__ int    g_cur[MAXN];
__device__ int    g_csr[MAXE + MAXN];
__device__ int    g_bsum[64];
__device__ int    g_is64;

__device__ __forceinline__ uint32_t cvt_tf32(uint32_t x) {
    uint32_t r;
    asm("cvt.rna.tf32.f32 %0, %1;" : "=r"(r) : "f"(__uint_as_float(x)));
    return r;
}

// ---------------- weight pre-conversion (rna) ----------------
__global__ void wconv_k(const float* __restrict__ W1, const float* __restrict__ W2) {
    int i = blockIdx.x * blockDim.x + threadIdx.x;
    int n1 = FIN * D1;
    int tot = n1 + D1 * OUTC;
    for (; i < tot; i += gridDim.x * blockDim.x) {
        if (i < n1) g_w1c[i] = __uint_as_float(cvt_tf32(__float_as_uint(W1[i])));
        else        g_w2c[i - n1] = __uint_as_float(cvt_tf32(__float_as_uint(W2[i - n1])));
    }
}

// ---------------- edge dtype detection ----------------
__global__ void detect_k(const unsigned* __restrict__ ew) {
    int t = threadIdx.x;  // 64 threads
    unsigned w = ew[2 * t + 1];
    unsigned nz = __ballot_sync(0xffffffffu, w != 0u);
    __shared__ unsigned s[2];
    if ((t & 31) == 0) s[t >> 5] = nz;
    __syncthreads();
    if (t == 0) g_is64 = ((s[0] | s[1]) == 0u) ? 1 : 0;
}

__device__ __forceinline__ int edge_at(const void* ew, int idx) {
    if (g_is64) return (int)((const long long*)ew)[idx];
    return ((const int*)ew)[idx];
}

// ---------------- CSR construction ----------------
__global__ void zero_deg_k(int n) {
    int i = blockIdx.x * blockDim.x + threadIdx.x;
    if (i < n) {
        g_deg[i] = 0;
        g_as2[i] = 0.f;
        g_ad2[i] = 0.f;
    }
}

__global__ void count_deg_k(const void* __restrict__ ew, int E, int N) {
    int e = blockIdx.x * blockDim.x + threadIdx.x;
    int ET = E + N;
    if (e >= ET) return;
    int dst = (e < E) ? edge_at(ew, E + e) : (e - E);
    if ((unsigned)dst < (unsigned)N) atomicAdd(&g_deg[dst], 1);
}

__global__ void scanA_k(int n) {
    __shared__ int s[1024];
    int t = threadIdx.x;
    int i = blockIdx.x * 1024 + t;
    int v = (i < n) ? g_deg[i] : 0;
    s[t] = v;
    __syncthreads();
#pragma unroll
    for (int off = 1; off < 1024; off <<= 1) {
        int tmp = (t >= off) ? s[t - off] : 0;
        __syncthreads();
        s[t] += tmp;
        __syncthreads();
    }
    if (i < n) g_off[i] = s[t] - v;
    if (t == 1023) g_bsum[blockIdx.x] = s[1023];
}

__global__ void scanB_k(int nb, int n) {
    int t = threadIdx.x;
    int v = (t < nb) ? g_bsum[t] : 0;
    int lane = t & 31;
    int incl = v;
#pragma unroll
    for (int off = 1; off < 32; off <<= 1) {
        int u = __shfl_up_sync(0xffffffffu, incl, off);
        if (lane >= off) incl += u;
    }
    __shared__ int wt[2];
    if (lane == 31) wt[t >> 5] = incl;
    __syncthreads();
    int add = (t >= 32) ? wt[0] : 0;
    incl += add;
    if (t < nb) g_bsum[t] = incl - v;
    if (t == 63) g_off[n] = incl;
}

__global__ void scanC_k(int n) {
    int t = threadIdx.x;
    int i = blockIdx.x * 1024 + t;
    if (i < n) {
        int o = g_off[i] + g_bsum[blockIdx.x];
        g_off[i] = o;
        g_cur[i] = o;
    }
}

__global__ void fill_csr_k(const void* __restrict__ ew, int E, int N) {
    int e = blockIdx.x * blockDim.x + threadIdx.x;
    int ET = E + N;
    if (e >= ET) return;
    int src, dst;
    if (e < E) { src = edge_at(ew, e); dst = edge_at(ew, E + e); }
    else       { src = e - E; dst = src; }
    if ((unsigned)dst >= (unsigned)N || (unsigned)src >= (unsigned)N) return;
    int pos = atomicAdd(&g_cur[dst], 1);
    g_csr[pos] = src;
}

// ---------------- TF32 tensor-core GEMM, 2-stage cp.async ----------------
// Epilogue: fp16 C store (gather format) + fused alpha from fp32 accumulators.
#define GA_PAD 20
#define GB_PAD 72

__device__ __forceinline__ void mma_tf32(float* c, const uint32_t* a, const uint32_t* b) {
    asm volatile(
        "mma.sync.aligned.m16n8k8.row.col.f32.tf32.tf32.f32 "
        "{%0,%1,%2,%3}, {%4,%5,%6,%7}, {%8,%9}, {%0,%1,%2,%3};"
        : "+f"(c[0]), "+f"(c[1]), "+f"(c[2]), "+f"(c[3])
        : "r"(a[0]), "r"(a[1]), "r"(a[2]), "r"(a[3]), "r"(b[0]), "r"(b[1]));
}

__device__ __forceinline__ void cp16(uint32_t smem, const float* gptr, bool valid) {
    int sz = valid ? 16 : 0;
    asm volatile("cp.async.cg.shared.global [%0], [%1], 16, %2;"
                 :: "r"(smem), "l"(gptr), "r"(sz));
}

template <int MODE>
__device__ __forceinline__ void gemm_tf32_body(const float* __restrict__ A,
                                               const float* __restrict__ B,
                                               __half* __restrict__ Ch,
                                               int M, int Nn, int K,
                                               const float* __restrict__ av_src,
                                               const float* __restrict__ av_dst) {
    __shared__ float As[2][128 * GA_PAD];
    __shared__ float Bs[2][16 * GB_PAD];

    int tid = threadIdx.x;
    int wid = tid >> 5, lane = tid & 31;
    int lq = lane >> 2, lr = lane & 3;
    int warp_m = wid & 3, warp_n = wid >> 2;
    int row0 = blockIdx.y * 128, col0 = blockIdx.x * 64;

    uint32_t as_base = (uint32_t)__cvta_generic_to_shared(&As[0][0]);
    uint32_t bs_base = (uint32_t)__cvta_generic_to_shared(&Bs[0][0]);
    const uint32_t as_stage = 128 * GA_PAD * 4;
    const uint32_t bs_stage = 16 * GB_PAD * 4;

    float acc[2][4][4];
#pragma unroll
    for (int i = 0; i < 2; i++)
#pragma unroll
        for (int j = 0; j < 4; j++)
#pragma unroll
            for (int q = 0; q < 4; q++) acc[i][j][q] = 0.f;

    int a_row[2], a_col[2];
#pragma unroll
    for (int u = 0; u < 2; u++) {
        int idx = tid + 256 * u;
        a_row[u] = idx >> 2;
        a_col[u] = (idx & 3) * 4;
    }
    int b_row = tid >> 4, b_col = (tid & 15) * 4;

    int nk = K >> 4;

    auto issue = [&](int kt, int stage) {
#pragma unroll
        for (int u = 0; u < 2; u++) {
            int r = row0 + a_row[u];
            bool v = (r < M);
            const float* gp = A + (long)(v ? r : 0) * K + (kt << 4) + a_col[u];
            cp16(as_base + stage * as_stage + (a_row[u] * GA_PAD + a_col[u]) * 4, gp, v);
        }
        const float* gp = B + (long)((kt << 4) + b_row) * Nn + col0 + b_col;
        cp16(bs_base + stage * bs_stage + (b_row * GB_PAD + b_col) * 4, gp, true);
        asm volatile("cp.async.commit_group;");
    };

    issue(0, 0);

    for (int kt = 0; kt < nk; kt++) {
        int stage = kt & 1;
        if (kt + 1 < nk) {
            issue(kt + 1, stage ^ 1);
            asm volatile("cp.async.wait_group 1;");
        } else {
            asm volatile("cp.async.wait_group 0;");
        }
        __syncthreads();

        const float* Asb = &As[stage][0];
        const float* Bsb = &Bs[stage][0];
#pragma unroll
        for (int kk = 0; kk < 16; kk += 8) {
            uint32_t af[2][4], bf[4][2];
#pragma unroll
            for (int tm = 0; tm < 2; tm++) {
                int bm = warp_m * 32 + tm * 16;
                const float* ap = Asb + kk + lr;
                af[tm][0] = cvt_tf32(__float_as_uint(ap[(bm + lq) * GA_PAD]));
                af[tm][1] = cvt_tf32(__float_as_uint(ap[(bm + lq + 8) * GA_PAD]));
                af[tm][2] = cvt_tf32(__float_as_uint(ap[(bm + lq) * GA_PAD + 4]));
                af[tm][3] = cvt_tf32(__float_as_uint(ap[(bm + lq + 8) * GA_PAD + 4]));
            }
#pragma unroll
            for (int tn = 0; tn < 4; tn++) {
                int bb = warp_n * 32 + tn * 8 + lq;
                bf[tn][0] = __float_as_uint(Bsb[(kk + lr) * GB_PAD + bb]);
                bf[tn][1] = __float_as_uint(Bsb[(kk + lr + 4) * GB_PAD + bb]);
            }
#pragma unroll
            for (int tm = 0; tm < 2; tm++)
#pragma unroll
                for (int tn = 0; tn < 4; tn++)
                    mma_tf32(acc[tm][tn], af[tm], bf[tn]);
        }
        __syncthreads();
    }

    // ---- store C as fp16 (half2 pairs) ----
#pragma unroll
    for (int tm = 0; tm < 2; tm++) {
        int r0 = row0 + warp_m * 32 + tm * 16 + lq;
#pragma unroll
        for (int tn = 0; tn < 4; tn++) {
            int c = col0 + warp_n * 32 + tn * 8 + 2 * lr;
            if (r0 < M) {
                __half2* p = (__half2*)(Ch + (long)r0 * Nn + c);
                *p = __floats2half2_rn(acc[tm][tn][0], acc[tm][tn][1]);
            }
            if (r0 + 8 < M) {
                __half2* p = (__half2*)(Ch + (long)(r0 + 8) * Nn + c);
                *p = __floats2half2_rn(acc[tm][tn][2], acc[tm][tn][3]);
            }
        }
    }

    // ---- fused alpha epilogue (from fp32 accumulators) ----
    float ps[2][2], pd[2][2];
#pragma unroll
    for (int tm = 0; tm < 2; tm++)
#pragma unroll
        for (int hf = 0; hf < 2; hf++) { ps[tm][hf] = 0.f; pd[tm][hf] = 0.f; }

#pragma unroll
    for (int tn = 0; tn < 4; tn++) {
        int ch = tn * 8 + 2 * lr;
        float s0, s1, d0, d1;
        if (MODE == 1) {
            int head = (col0 >> 5) + warp_n;
            s0 = av_src[head * C1 + ch];     s1 = av_src[head * C1 + ch + 1];
            d0 = av_dst[head * C1 + ch];     d1 = av_dst[head * C1 + ch + 1];
        } else {
            int c = warp_n * 32 + ch;
            s0 = av_src[c]; s1 = av_src[c + 1];
            d0 = av_dst[c]; d1 = av_dst[c + 1];
        }
#pragma unroll
        for (int tm = 0; tm < 2; tm++) {
            ps[tm][0] = fmaf(s0, acc[tm][tn][0], fmaf(s1, acc[tm][tn][1], ps[tm][0]));
            ps[tm][1] = fmaf(s0, acc[tm][tn][2], fmaf(s1, acc[tm][tn][3], ps[tm][1]));
            pd[tm][0] = fmaf(d0, acc[tm][tn][0], fmaf(d1, acc[tm][tn][1], pd[tm][0]));
            pd[tm][1] = fmaf(d0, acc[tm][tn][2], fmaf(d1, acc[tm][tn][3], pd[tm][1]));
        }
    }
#pragma unroll
    for (int tm = 0; tm < 2; tm++)
#pragma unroll
        for (int hf = 0; hf < 2; hf++) {
            ps[tm][hf] += __shfl_xor_sync(0xffffffffu, ps[tm][hf], 1);
            ps[tm][hf] += __shfl_xor_sync(0xffffffffu, ps[tm][hf], 2);
            pd[tm][hf] += __shfl_xor_sync(0xffffffffu, pd[tm][hf], 1);
            pd[tm][hf] += __shfl_xor_sync(0xffffffffu, pd[tm][hf], 2);
        }
    if (lr == 0) {
#pragma unroll
        for (int tm = 0; tm < 2; tm++)
#pragma unroll
            for (int hf = 0; hf < 2; hf++) {
                int r = row0 + warp_m * 32 + tm * 16 + lq + hf * 8;
                if (r < M) {
                    if (MODE == 1) {
                        int head = (col0 >> 5) + warp_n;
                        g_as1[r * H1 + head] = ps[tm][hf];
                        g_ad1[r * H1 + head] = pd[tm][hf];
                    } else {
                        atomicAdd(&g_as2[r], ps[tm][hf]);
                        atomicAdd(&g_ad2[r], pd[tm][hf]);
                    }
                }
            }
    }
}

__global__ void gemm1_k(const float* __restrict__ A, int M,
                        const float* __restrict__ av_src, const float* __restrict__ av_dst) {
    gemm_tf32_body<1>(A, g_w1c, g_xw1h, M, D1, FIN, av_src, av_dst);
}
__global__ void gemm2_k(int M,
                        const float* __restrict__ av_src, const float* __restrict__ av_dst) {
    gemm_tf32_body<2>(g_h, g_w2c, g_h2h, M, OUTC, D1, av_src, av_dst);
}

// ---------------- layer-1 aggregation: one WARP per node, SINGLE pass, fp16 gather ----
__global__ void agg1_k(const float* __restrict__ b1, int N) {
    int warp = (blockIdx.x * blockDim.x + threadIdx.x) >> 5;
    if (warp >= N) return;
    int n = warp;
    int lane = threadIdx.x & 31;
    int beg = g_off[n], end = g_off[n + 1];

    float ad = (lane < H1) ? g_ad1[n * H1 + lane] : 0.f;

    float denom = 0.f;
    float acc[H1];
#pragma unroll
    for (int h = 0; h < H1; h++) acc[h] = 0.f;

    for (int k = beg; k < end; k++) {
        int s = g_csr[k];
        float as = (lane < H1) ? g_as1[s * H1 + lane] : 0.f;
        float e = as + ad;
        e = (e > 0.f) ? e : 0.2f * e;
        float w = __expf(e);
        denom += w;
        const __half* row = g_xw1h + s * D1;
#pragma unroll
        for (int h = 0; h < H1; h++) {
            float wh = __shfl_sync(0xffffffffu, w, h);
            acc[h] = fmaf(wh, __half2float(row[h * C1 + lane]), acc[h]);
        }
    }
    float inv = 1.f / (denom + 1e-16f);

#pragma unroll
    for (int h = 0; h < H1; h++) {
        float invh = __shfl_sync(0xffffffffu, inv, h);
        float v = acc[h] * invh + b1[h * C1 + lane];
        v = (v > 0.f) ? v : (__expf(v) - 1.f);
        g_h[n * D1 + h * C1 + lane] = v;
    }
}

// ---------------- layer-2 aggregation + bias + log_softmax: fp16 gather ----------------
__global__ void agg2_k(const float* __restrict__ b2, float* __restrict__ out, int N) {
    int warp = (blockIdx.x * blockDim.x + threadIdx.x) >> 5;
    if (warp >= N) return;
    int n = warp;
    int lane = threadIdx.x & 31;
    int beg = g_off[n], end = g_off[n + 1];
    float ad = g_ad2[n];

    float denom = 0.f, a0 = 0.f, a1 = 0.f;
    for (int k = beg; k < end; k++) {
        int s = g_csr[k];
        float e = g_as2[s] + ad;
        e = (e > 0.f) ? e : 0.2f * e;
        float w = __expf(e);
        denom += w;
        const __half* row = g_h2h + s * OUTC;
        a0 = fmaf(w, __half2float(row[lane]), a0);
        a1 = fmaf(w, __half2float(row[32 + lane]), a1);
    }
    float inv = 1.f / (denom + 1e-16f);
    a0 = a0 * inv + b2[lane];
    a1 = a1 * inv + b2[32 + lane];

    float mx = fmaxf(a0, a1);
#pragma unroll
    for (int o = 16; o; o >>= 1) mx = fmaxf(mx, __shfl_xor_sync(0xffffffffu, mx, o));
    float sum = __expf(a0 - mx) + __expf(a1 - mx);
#pragma unroll
    for (int o = 16; o; o >>= 1) sum += __shfl_xor_sync(0xffffffffu, sum, o);
    float lse = mx + __logf(sum);
    out[n * OUTC + lane] = a0 - lse;
    out[n * OUTC + 32 + lane] = a1 - lse;
}

// ---------------- launch ----------------
extern "C" void kernel_launch(void* const* d_in, const int* in_sizes, int n_in,
                              void* d_out, int out_size) {
    const float* x   = (const float*)d_in[0];
    const void*  ei  = d_in[1];
    const float* W1  = (const float*)d_in[2];
    const float* as1 = (const float*)d_in[3];
    const float* ad1 = (const float*)d_in[4];
    const float* b1  = (const float*)d_in[5];
    const float* W2  = (const float*)d_in[6];
    const float* as2 = (const float*)d_in[7];
    const float* ad2 = (const float*)d_in[8];
    const float* b2  = (const float*)d_in[9];
    float* out = (float*)d_out;

    int E = in_sizes[1] / 2;
    int N = in_sizes[0] / FIN;
    int ET = E + N;
    int nb = (N + 1023) / 1024;

    cudaStream_t s2;
    cudaStreamCreateWithFlags(&s2, cudaStreamNonBlocking);
    cudaEvent_t eFork, eJoin;
    cudaEventCreateWithFlags(&eFork, cudaEventDisableTiming);
    cudaEventCreateWithFlags(&eJoin, cudaEventDisableTiming);

    cudaEventRecord(eFork, 0);
    cudaStreamWaitEvent(s2, eFork, 0);

    // --- branch A (s2): CSR construction ---
    detect_k<<<1, 64, 0, s2>>>((const unsigned*)ei);
    zero_deg_k<<<(N + 255) / 256, 256, 0, s2>>>(N);
    count_deg_k<<<(ET + 255) / 256, 256, 0, s2>>>(ei, E, N);
    scanA_k<<<nb, 1024, 0, s2>>>(N);
    scanB_k<<<1, 64, 0, s2>>>(nb, N);
    scanC_k<<<nb, 1024, 0, s2>>>(N);
    fill_csr_k<<<(ET + 255) / 256, 256, 0, s2>>>(ei, E, N);
    cudaEventRecord(eJoin, s2);

    // --- branch B (default stream): weights + GEMM1 + fused alpha1 ---
    wconv_k<<<160, 256>>>(W1, W2);
    {
        dim3 grid(D1 / 64, (N + 127) / 128);
        gemm1_k<<<grid, 256>>>(x, N, as1, ad1);
    }

    cudaStreamWaitEvent(0, eJoin, 0);

    agg1_k<<<(N * 32 + 255) / 256, 256>>>(b1, N);
    {
        dim3 grid(OUTC / 64, (N + 127) / 128);
        gemm2_k<<<grid, 256>>>(N, as2, ad2);
    }
    agg2_k<<<(N * 32 + 255) / 256, 256>>>(b2, out, N);

    cudaEventDestroy(eFork);
    cudaEventDestroy(eJoin);
    cudaStreamDestroy(s2);
}

// round 12
// speedup vs baseline: 4.8006x; 1.0873x over previous
#include <cuda_runtime.h>
#include <cuda_fp16.h>
#include <math.h>
#include <stdint.h>

// ---------------- problem constants (fixed shapes) ----------------
#define MAXN 50000
#define MAXE 800000
#define FIN  512
#define D1   256      // H1 * C1
#define H1   8
#define C1   32
#define OUTC 64

// ---------------- scratch ----------------
__device__ __half g_xw1h[MAXN * D1];   // layer1 linear output, fp16 (gather format)
__device__ float  g_h[MAXN * D1];      // layer1 activation (fp32, gemm2 input)
__device__ __half g_h2h[MAXN * OUTC];  // layer2 linear output, fp16 (gather format)
__device__ float  g_as1[MAXN * H1];
__device__ float  g_ad1[MAXN * H1];
__device__ float  g_as2[MAXN];
__device__ float  g_ad2[MAXN];
__device__ float  g_w1c[FIN * D1];     // W1 pre-rounded to tf32 (rna)
__device__ float  g_w2c[D1 * OUTC];    // W2 pre-rounded to tf32 (rna)
__device__ int    g_deg[MAXN];
__device__ int    g_off[MAXN + 1];
__device__ int    g_cur[MAXN];
__device__ int    g_csr[MAXE + MAXN];
__device__ int    g_bsum[64];
__device__ int    g_is64;

__device__ __forceinline__ uint32_t cvt_tf32(uint32_t x) {
    uint32_t r;
    asm("cvt.rna.tf32.f32 %0, %1;" : "=r"(r) : "f"(__uint_as_float(x)));
    return r;
}

// ---------------- weight pre-conversion (rna) ----------------
__global__ void wconv_k(const float* __restrict__ W1, const float* __restrict__ W2) {
    int i = blockIdx.x * blockDim.x + threadIdx.x;
    int n1 = FIN * D1;
    int tot = n1 + D1 * OUTC;
    for (; i < tot; i += gridDim.x * blockDim.x) {
        if (i < n1) g_w1c[i] = __uint_as_float(cvt_tf32(__float_as_uint(W1[i])));
        else        g_w2c[i - n1] = __uint_as_float(cvt_tf32(__float_as_uint(W2[i - n1])));
    }
}

// ---------------- edge dtype detection ----------------
__global__ void detect_k(const unsigned* __restrict__ ew) {
    int t = threadIdx.x;  // 64 threads
    unsigned w = ew[2 * t + 1];
    unsigned nz = __ballot_sync(0xffffffffu, w != 0u);
    __shared__ unsigned s[2];
    if ((t & 31) == 0) s[t >> 5] = nz;
    __syncthreads();
    if (t == 0) g_is64 = ((s[0] | s[1]) == 0u) ? 1 : 0;
}

__device__ __forceinline__ int edge_at(const void* ew, int idx) {
    if (g_is64) return (int)((const long long*)ew)[idx];
    return ((const int*)ew)[idx];
}

// ---------------- CSR construction ----------------
__global__ void zero_deg_k(int n) {
    int i = blockIdx.x * blockDim.x + threadIdx.x;
    if (i < n) {
        g_deg[i] = 0;
        g_as2[i] = 0.f;
        g_ad2[i] = 0.f;
    }
}

__global__ void count_deg_k(const void* __restrict__ ew, int E, int N) {
    int e = blockIdx.x * blockDim.x + threadIdx.x;
    int ET = E + N;
    if (e >= ET) return;
    int dst = (e < E) ? edge_at(ew, E + e) : (e - E);
    if ((unsigned)dst < (unsigned)N) atomicAdd(&g_deg[dst], 1);
}

__global__ void scanA_k(int n) {
    __shared__ int s[1024];
    int t = threadIdx.x;
    int i = blockIdx.x * 1024 + t;
    int v = (i < n) ? g_deg[i] : 0;
    s[t] = v;
    __syncthreads();
#pragma unroll
    for (int off = 1; off < 1024; off <<= 1) {
        int tmp = (t >= off) ? s[t - off] : 0;
        __syncthreads();
        s[t] += tmp;
        __syncthreads();
    }
    if (i < n) g_off[i] = s[t] - v;
    if (t == 1023) g_bsum[blockIdx.x] = s[1023];
}

__global__ void scanB_k(int nb, int n) {
    int t = threadIdx.x;
    int v = (t < nb) ? g_bsum[t] : 0;
    int lane = t & 31;
    int incl = v;
#pragma unroll
    for (int off = 1; off < 32; off <<= 1) {
        int u = __shfl_up_sync(0xffffffffu, incl, off);
        if (lane >= off) incl += u;
    }
    __shared__ int wt[2];
    if (lane == 31) wt[t >> 5] = incl;
    __syncthreads();
    int add = (t >= 32) ? wt[0] : 0;
    incl += add;
    if (t < nb) g_bsum[t] = incl - v;
    if (t == 63) g_off[n] = incl;
}

__global__ void scanC_k(int n) {
    int t = threadIdx.x;
    int i = blockIdx.x * 1024 + t;
    if (i < n) {
        int o = g_off[i] + g_bsum[blockIdx.x];
        g_off[i] = o;
        g_cur[i] = o;
    }
}

__global__ void fill_csr_k(const void* __restrict__ ew, int E, int N) {
    int e = blockIdx.x * blockDim.x + threadIdx.x;
    int ET = E + N;
    if (e >= ET) return;
    int src, dst;
    if (e < E) { src = edge_at(ew, e); dst = edge_at(ew, E + e); }
    else       { src = e - E; dst = src; }
    if ((unsigned)dst >= (unsigned)N || (unsigned)src >= (unsigned)N) return;
    int pos = atomicAdd(&g_cur[dst], 1);
    g_csr[pos] = src;
}

// ---------------- TF32 tensor-core GEMM, 2-stage cp.async ----------------
#define GA_PAD 20
#define GB_PAD 72

__device__ __forceinline__ void mma_tf32(float* c, const uint32_t* a, const uint32_t* b) {
    asm volatile(
        "mma.sync.aligned.m16n8k8.row.col.f32.tf32.tf32.f32 "
        "{%0,%1,%2,%3}, {%4,%5,%6,%7}, {%8,%9}, {%0,%1,%2,%3};"
        : "+f"(c[0]), "+f"(c[1]), "+f"(c[2]), "+f"(c[3])
        : "r"(a[0]), "r"(a[1]), "r"(a[2]), "r"(a[3]), "r"(b[0]), "r"(b[1]));
}

__device__ __forceinline__ void cp16(uint32_t smem, const float* gptr, bool valid) {
    int sz = valid ? 16 : 0;
    asm volatile("cp.async.cg.shared.global [%0], [%1], 16, %2;"
                 :: "r"(smem), "l"(gptr), "r"(sz));
}

template <int MODE>
__device__ __forceinline__ void gemm_tf32_body(const float* __restrict__ A,
                                               const float* __restrict__ B,
                                               __half* __restrict__ Ch,
                                               int M, int Nn, int K,
                                               const float* __restrict__ av_src,
                                               const float* __restrict__ av_dst) {
    __shared__ float As[2][128 * GA_PAD];
    __shared__ float Bs[2][16 * GB_PAD];

    int tid = threadIdx.x;
    int wid = tid >> 5, lane = tid & 31;
    int lq = lane >> 2, lr = lane & 3;
    int warp_m = wid & 3, warp_n = wid >> 2;
    int row0 = blockIdx.y * 128, col0 = blockIdx.x * 64;

    uint32_t as_base = (uint32_t)__cvta_generic_to_shared(&As[0][0]);
    uint32_t bs_base = (uint32_t)__cvta_generic_to_shared(&Bs[0][0]);
    const uint32_t as_stage = 128 * GA_PAD * 4;
    const uint32_t bs_stage = 16 * GB_PAD * 4;

    float acc[2][4][4];
#pragma unroll
    for (int i = 0; i < 2; i++)
#pragma unroll
        for (int j = 0; j < 4; j++)
#pragma unroll
            for (int q = 0; q < 4; q++) acc[i][j][q] = 0.f;

    int a_row[2], a_col[2];
#pragma unroll
    for (int u = 0; u < 2; u++) {
        int idx = tid + 256 * u;
        a_row[u] = idx >> 2;
        a_col[u] = (idx & 3) * 4;
    }
    int b_row = tid >> 4, b_col = (tid & 15) * 4;

    int nk = K >> 4;

    auto issue = [&](int kt, int stage) {
#pragma unroll
        for (int u = 0; u < 2; u++) {
            int r = row0 + a_row[u];
            bool v = (r < M);
            const float* gp = A + (long)(v ? r : 0) * K + (kt << 4) + a_col[u];
            cp16(as_base + stage * as_stage + (a_row[u] * GA_PAD + a_col[u]) * 4, gp, v);
        }
        const float* gp = B + (long)((kt << 4) + b_row) * Nn + col0 + b_col;
        cp16(bs_base + stage * bs_stage + (b_row * GB_PAD + b_col) * 4, gp, true);
        asm volatile("cp.async.commit_group;");
    };

    issue(0, 0);

    for (int kt = 0; kt < nk; kt++) {
        int stage = kt & 1;
        if (kt + 1 < nk) {
            issue(kt + 1, stage ^ 1);
            asm volatile("cp.async.wait_group 1;");
        } else {
            asm volatile("cp.async.wait_group 0;");
        }
        __syncthreads();

        const float* Asb = &As[stage][0];
        const float* Bsb = &Bs[stage][0];
#pragma unroll
        for (int kk = 0; kk < 16; kk += 8) {
            uint32_t af[2][4], bf[4][2];
#pragma unroll
            for (int tm = 0; tm < 2; tm++) {
                int bm = warp_m * 32 + tm * 16;
                const float* ap = Asb + kk + lr;
                af[tm][0] = cvt_tf32(__float_as_uint(ap[(bm + lq) * GA_PAD]));
                af[tm][1] = cvt_tf32(__float_as_uint(ap[(bm + lq + 8) * GA_PAD]));
                af[tm][2] = cvt_tf32(__float_as_uint(ap[(bm + lq) * GA_PAD + 4]));
                af[tm][3] = cvt_tf32(__float_as_uint(ap[(bm + lq + 8) * GA_PAD + 4]));
            }
#pragma unroll
            for (int tn = 0; tn < 4; tn++) {
                int bb = warp_n * 32 + tn * 8 + lq;
                bf[tn][0] = __float_as_uint(Bsb[(kk + lr) * GB_PAD + bb]);
                bf[tn][1] = __float_as_uint(Bsb[(kk + lr + 4) * GB_PAD + bb]);
            }
#pragma unroll
            for (int tm = 0; tm < 2; tm++)
#pragma unroll
                for (int tn = 0; tn < 4; tn++)
                    mma_tf32(acc[tm][tn], af[tm], bf[tn]);
        }
        __syncthreads();
    }

    // ---- store C as fp16 (half2 pairs) ----
#pragma unroll
    for (int tm = 0; tm < 2; tm++) {
        int r0 = row0 + warp_m * 32 + tm * 16 + lq;
#pragma unroll
        for (int tn = 0; tn < 4; tn++) {
            int c = col0 + warp_n * 32 + tn * 8 + 2 * lr;
            if (r0 < M) {
                __half2* p = (__half2*)(Ch + (long)r0 * Nn + c);
                *p = __floats2half2_rn(acc[tm][tn][0], acc[tm][tn][1]);
            }
            if (r0 + 8 < M) {
                __half2* p = (__half2*)(Ch + (long)(r0 + 8) * Nn + c);
                *p = __floats2half2_rn(acc[tm][tn][2], acc[tm][tn][3]);
            }
        }
    }

    // ---- fused alpha epilogue (from fp32 accumulators) ----
    float ps[2][2], pd[2][2];
#pragma unroll
    for (int tm = 0; tm < 2; tm++)
#pragma unroll
        for (int hf = 0; hf < 2; hf++) { ps[tm][hf] = 0.f; pd[tm][hf] = 0.f; }

#pragma unroll
    for (int tn = 0; tn < 4; tn++) {
        int ch = tn * 8 + 2 * lr;
        float s0, s1, d0, d1;
        if (MODE == 1) {
            int head = (col0 >> 5) + warp_n;
            s0 = av_src[head * C1 + ch];     s1 = av_src[head * C1 + ch + 1];
            d0 = av_dst[head * C1 + ch];     d1 = av_dst[head * C1 + ch + 1];
        } else {
            int c = warp_n * 32 + ch;
            s0 = av_src[c]; s1 = av_src[c + 1];
            d0 = av_dst[c]; d1 = av_dst[c + 1];
        }
#pragma unroll
        for (int tm = 0; tm < 2; tm++) {
            ps[tm][0] = fmaf(s0, acc[tm][tn][0], fmaf(s1, acc[tm][tn][1], ps[tm][0]));
            ps[tm][1] = fmaf(s0, acc[tm][tn][2], fmaf(s1, acc[tm][tn][3], ps[tm][1]));
            pd[tm][0] = fmaf(d0, acc[tm][tn][0], fmaf(d1, acc[tm][tn][1], pd[tm][0]));
            pd[tm][1] = fmaf(d0, acc[tm][tn][2], fmaf(d1, acc[tm][tn][3], pd[tm][1]));
        }
    }
#pragma unroll
    for (int tm = 0; tm < 2; tm++)
#pragma unroll
        for (int hf = 0; hf < 2; hf++) {
            ps[tm][hf] += __shfl_xor_sync(0xffffffffu, ps[tm][hf], 1);
            ps[tm][hf] += __shfl_xor_sync(0xffffffffu, ps[tm][hf], 2);
            pd[tm][hf] += __shfl_xor_sync(0xffffffffu, pd[tm][hf], 1);
            pd[tm][hf] += __shfl_xor_sync(0xffffffffu, pd[tm][hf], 2);
        }
    if (lr == 0) {
#pragma unroll
        for (int tm = 0; tm < 2; tm++)
#pragma unroll
            for (int hf = 0; hf < 2; hf++) {
                int r = row0 + warp_m * 32 + tm * 16 + lq + hf * 8;
                if (r < M) {
                    if (MODE == 1) {
                        int head = (col0 >> 5) + warp_n;
                        g_as1[r * H1 + head] = ps[tm][hf];
                        g_ad1[r * H1 + head] = pd[tm][hf];
                    } else {
                        atomicAdd(&g_as2[r], ps[tm][hf]);
                        atomicAdd(&g_ad2[r], pd[tm][hf]);
                    }
                }
            }
    }
}

__global__ void gemm1_k(const float* __restrict__ A, int M,
                        const float* __restrict__ av_src, const float* __restrict__ av_dst) {
    gemm_tf32_body<1>(A, g_w1c, g_xw1h, M, D1, FIN, av_src, av_dst);
}
__global__ void gemm2_k(int M,
                        const float* __restrict__ av_src, const float* __restrict__ av_dst) {
    gemm_tf32_body<2>(g_h, g_w2c, g_h2h, M, OUTC, D1, av_src, av_dst);
}

// ---------------- layer-1 aggregation: one WARP per node, 1x LDG.128 per edge ----
// lane i holds halves 8i..8i+7 of the 256-half xw row = head i/4, channels (i%4)*8..+7.
__global__ void agg1_k(const float* __restrict__ b1, int N) {
    int warp = (blockIdx.x * blockDim.x + threadIdx.x) >> 5;
    if (warp >= N) return;
    int n = warp;
    int lane = threadIdx.x & 31;
    int beg = g_off[n], end = g_off[n + 1];
    int src_lane = lane >> 2;            // head owner lane (0..7)

    float ad = (lane < H1) ? g_ad1[n * H1 + lane] : 0.f;

    float denom = 0.f;
    float acc[8];
#pragma unroll
    for (int j = 0; j < 8; j++) acc[j] = 0.f;

    for (int k = beg; k < end; k++) {
        int s = g_csr[k];
        float as = (lane < H1) ? g_as1[s * H1 + lane] : 0.f;
        float e = as + ad;
        e = (e > 0.f) ? e : 0.2f * e;
        float w = __expf(e);             // valid in lanes 0..7
        denom += w;
        float wh = __shfl_sync(0xffffffffu, w, src_lane);
        uint4 pkt = *(const uint4*)(g_xw1h + (long)s * D1 + lane * 8);
#pragma unroll
        for (int q = 0; q < 4; q++) {
            uint32_t u = (q == 0) ? pkt.x : (q == 1) ? pkt.y : (q == 2) ? pkt.z : pkt.w;
            float2 f = __half22float2(*(__half2*)&u);
            acc[2 * q]     = fmaf(wh, f.x, acc[2 * q]);
            acc[2 * q + 1] = fmaf(wh, f.y, acc[2 * q + 1]);
        }
    }
    float inv = 1.f / (denom + 1e-16f);  // per-head in lanes 0..7
    float invh = __shfl_sync(0xffffffffu, inv, src_lane);

    // lane i writes channels 8i..8i+7 (contiguous warp-wide 1KB row)
    float o[8];
#pragma unroll
    for (int j = 0; j < 8; j++) {
        float v = acc[j] * invh + b1[lane * 8 + j];
        o[j] = (v > 0.f) ? v : (__expf(v) - 1.f);
    }
    float4* dst = (float4*)(g_h + (long)n * D1 + lane * 8);
    dst[0] = make_float4(o[0], o[1], o[2], o[3]);
    dst[1] = make_float4(o[4], o[5], o[6], o[7]);
}

// ---------------- layer-2 aggregation + bias + log_softmax: 1x LDG.64 per edge ----
// lane i holds channels 2i, 2i+1 of the 64-half h2 row.
__global__ void agg2_k(const float* __restrict__ b2, float* __restrict__ out, int N) {
    int warp = (blockIdx.x * blockDim.x + threadIdx.x) >> 5;
    if (warp >= N) return;
    int n = warp;
    int lane = threadIdx.x & 31;
    int beg = g_off[n], end = g_off[n + 1];
    float ad = g_ad2[n];

    float denom = 0.f, a0 = 0.f, a1 = 0.f;
    for (int k = beg; k < end; k++) {
        int s = g_csr[k];
        float e = g_as2[s] + ad;         // uniform across lanes
        e = (e > 0.f) ? e : 0.2f * e;
        float w = __expf(e);
        denom += w;
        __half2 hv = *(const __half2*)(g_h2h + (long)s * OUTC + lane * 2);
        float2 f = __half22float2(hv);
        a0 = fmaf(w, f.x, a0);
        a1 = fmaf(w, f.y, a1);
    }
    float inv = 1.f / (denom + 1e-16f);
    a0 = a0 * inv + b2[lane * 2];
    a1 = a1 * inv + b2[lane * 2 + 1];

    float mx = fmaxf(a0, a1);
#pragma unroll
    for (int o = 16; o; o >>= 1) mx = fmaxf(mx, __shfl_xor_sync(0xffffffffu, mx, o));
    float sum = __expf(a0 - mx) + __expf(a1 - mx);
#pragma unroll
    for (int o = 16; o; o >>= 1) sum += __shfl_xor_sync(0xffffffffu, sum, o);
    float lse = mx + __logf(sum);
    float2* po = (float2*)(out + (long)n * OUTC + lane * 2);
    *po = make_float2(a0 - lse, a1 - lse);
}

// ---------------- launch ----------------
extern "C" void kernel_launch(void* const* d_in, const int* in_sizes, int n_in,
                              void* d_out, int out_size) {
    const float* x   = (const float*)d_in[0];
    const void*  ei  = d_in[1];
    const float* W1  = (const float*)d_in[2];
    const float* as1 = (const float*)d_in[3];
    const float* ad1 = (const float*)d_in[4];
    const float* b1  = (const float*)d_in[5];
    const float* W2  = (const float*)d_in[6];
    const float* as2 = (const float*)d_in[7];
    const float* ad2 = (const float*)d_in[8];
    const float* b2  = (const float*)d_in[9];
    float* out = (float*)d_out;

    int E = in_sizes[1] / 2;
    int N = in_sizes[0] / FIN;
    int ET = E + N;
    int nb = (N + 1023) / 1024;

    cudaStream_t s2;
    cudaStreamCreateWithFlags(&s2, cudaStreamNonBlocking);
    cudaEvent_t eFork, eJoin;
    cudaEventCreateWithFlags(&eFork, cudaEventDisableTiming);
    cudaEventCreateWithFlags(&eJoin, cudaEventDisableTiming);

    cudaEventRecord(eFork, 0);
    cudaStreamWaitEvent(s2, eFork, 0);

    // --- branch A (s2): CSR construction ---
    detect_k<<<1, 64, 0, s2>>>((const unsigned*)ei);
    zero_deg_k<<<(N + 255) / 256, 256, 0, s2>>>(N);
    count_deg_k<<<(ET + 255) / 256, 256, 0, s2>>>(ei, E, N);
    scanA_k<<<nb, 1024, 0, s2>>>(N);
    scanB_k<<<1, 64, 0, s2>>>(nb, N);
    scanC_k<<<nb, 1024, 0, s2>>>(N);
    fill_csr_k<<<(ET + 255) / 256, 256, 0, s2>>>(ei, E, N);
    cudaEventRecord(eJoin, s2);

    // --- branch B (default stream): weights + GEMM1 + fused alpha1 ---
    wconv_k<<<160, 256>>>(W1, W2);
    {
        dim3 grid(D1 / 64, (N + 127) / 128);
        gemm1_k<<<grid, 256>>>(x, N, as1, ad1);
    }

    cudaStreamWaitEvent(0, eJoin, 0);

    agg1_k<<<(N * 32 + 255) / 256, 256>>>(b1, N);
    {
        dim3 grid(OUTC / 64, (N + 127) / 128);
        gemm2_k<<<grid, 256>>>(N, as2, ad2);
    }
    agg2_k<<<(N * 32 + 255) / 256, 256>>>(b2, out, N);

    cudaEventDestroy(eFork);
    cudaEventDestroy(eJoin);
    cudaStreamDestroy(s2);
}

// round 13
// speedup vs baseline: 5.2763x; 1.0991x over previous
#include <cuda_runtime.h>
#include <cuda_fp16.h>
#include <math.h>
#include <stdint.h>

// ---------------- problem constants (fixed shapes) ----------------
#define MAXN 50000
#define MAXE 800000
#define FIN  512
#define D1   256      // H1 * C1
#define H1   8
#define C1   32
#define OUTC 64

// ---------------- scratch ----------------
__device__ __half g_xw1h[MAXN * D1];   // layer1 linear output, fp16 (gather format)
__device__ float  g_h[MAXN * D1];      // layer1 activation (fp32, gemm2 input)
__device__ __half g_h2h[MAXN * OUTC];  // layer2 linear output, fp16 (gather format)
__device__ float  g_as1[MAXN * H1];
__device__ float  g_ad1[MAXN * H1];
__device__ float  g_as2[MAXN];
__device__ float  g_ad2[MAXN];
__device__ float  g_w1c[FIN * D1];     // W1 pre-rounded to tf32 (rna)
__device__ float  g_w2c[D1 * OUTC];    // W2 pre-rounded to tf32 (rna)
__device__ int    g_deg[MAXN];
__device__ int    g_off[MAXN + 1];
__device__ int    g_cur[MAXN];
__device__ int    g_csr[MAXE + MAXN];
__device__ int    g_bsum[64];
__device__ int    g_is64;

__device__ __forceinline__ uint32_t cvt_tf32(uint32_t x) {
    uint32_t r;
    asm("cvt.rna.tf32.f32 %0, %1;" : "=r"(r) : "f"(__uint_as_float(x)));
    return r;
}

// ---------------- weight pre-conversion (rna) ----------------
__global__ void wconv_k(const float* __restrict__ W1, const float* __restrict__ W2) {
    int i = blockIdx.x * blockDim.x + threadIdx.x;
    int n1 = FIN * D1;
    int tot = n1 + D1 * OUTC;
    for (; i < tot; i += gridDim.x * blockDim.x) {
        if (i < n1) g_w1c[i] = __uint_as_float(cvt_tf32(__float_as_uint(W1[i])));
        else        g_w2c[i - n1] = __uint_as_float(cvt_tf32(__float_as_uint(W2[i - n1])));
    }
}

// ---------------- edge dtype detection ----------------
__global__ void detect_k(const unsigned* __restrict__ ew) {
    int t = threadIdx.x;  // 64 threads
    unsigned w = ew[2 * t + 1];
    unsigned nz = __ballot_sync(0xffffffffu, w != 0u);
    __shared__ unsigned s[2];
    if ((t & 31) == 0) s[t >> 5] = nz;
    __syncthreads();
    if (t == 0) g_is64 = ((s[0] | s[1]) == 0u) ? 1 : 0;
}

__device__ __forceinline__ int edge_at(const void* ew, int idx) {
    if (g_is64) return (int)((const long long*)ew)[idx];
    return ((const int*)ew)[idx];
}

// ---------------- CSR construction ----------------
__global__ void zero_deg_k(int n) {
    int i = blockIdx.x * blockDim.x + threadIdx.x;
    if (i < n) {
        g_deg[i] = 0;
        g_as2[i] = 0.f;
        g_ad2[i] = 0.f;
    }
}

__global__ void count_deg_k(const void* __restrict__ ew, int E, int N) {
    int e = blockIdx.x * blockDim.x + threadIdx.x;
    int ET = E + N;
    if (e >= ET) return;
    int dst = (e < E) ? edge_at(ew, E + e) : (e - E);
    if ((unsigned)dst < (unsigned)N) atomicAdd(&g_deg[dst], 1);
}

__global__ void scanA_k(int n) {
    __shared__ int s[1024];
    int t = threadIdx.x;
    int i = blockIdx.x * 1024 + t;
    int v = (i < n) ? g_deg[i] : 0;
    s[t] = v;
    __syncthreads();
#pragma unroll
    for (int off = 1; off < 1024; off <<= 1) {
        int tmp = (t >= off) ? s[t - off] : 0;
        __syncthreads();
        s[t] += tmp;
        __syncthreads();
    }
    if (i < n) g_off[i] = s[t] - v;
    if (t == 1023) g_bsum[blockIdx.x] = s[1023];
}

__global__ void scanB_k(int nb, int n) {
    int t = threadIdx.x;
    int v = (t < nb) ? g_bsum[t] : 0;
    int lane = t & 31;
    int incl = v;
#pragma unroll
    for (int off = 1; off < 32; off <<= 1) {
        int u = __shfl_up_sync(0xffffffffu, incl, off);
        if (lane >= off) incl += u;
    }
    __shared__ int wt[2];
    if (lane == 31) wt[t >> 5] = incl;
    __syncthreads();
    int add = (t >= 32) ? wt[0] : 0;
    incl += add;
    if (t < nb) g_bsum[t] = incl - v;
    if (t == 63) g_off[n] = incl;
}

__global__ void scanC_k(int n) {
    int t = threadIdx.x;
    int i = blockIdx.x * 1024 + t;
    if (i < n) {
        int o = g_off[i] + g_bsum[blockIdx.x];
        g_off[i] = o;
        g_cur[i] = o;
    }
}

__global__ void fill_csr_k(const void* __restrict__ ew, int E, int N) {
    int e = blockIdx.x * blockDim.x + threadIdx.x;
    int ET = E + N;
    if (e >= ET) return;
    int src, dst;
    if (e < E) { src = edge_at(ew, e); dst = edge_at(ew, E + e); }
    else       { src = e - E; dst = src; }
    if ((unsigned)dst >= (unsigned)N || (unsigned)src >= (unsigned)N) return;
    int pos = atomicAdd(&g_cur[dst], 1);
    g_csr[pos] = src;
}

// ---------------- TF32 tensor-core GEMM, 2-stage cp.async, templated BN ----------------
// BM=128, BN in {64,128}; 256 threads = 8 warps (4 M x 2 N); warp tile 32 x BN/2.
#define GA_PAD 20

__device__ __forceinline__ void mma_tf32(float* c, const uint32_t* a, const uint32_t* b) {
    asm volatile(
        "mma.sync.aligned.m16n8k8.row.col.f32.tf32.tf32.f32 "
        "{%0,%1,%2,%3}, {%4,%5,%6,%7}, {%8,%9}, {%0,%1,%2,%3};"
        : "+f"(c[0]), "+f"(c[1]), "+f"(c[2]), "+f"(c[3])
        : "r"(a[0]), "r"(a[1]), "r"(a[2]), "r"(a[3]), "r"(b[0]), "r"(b[1]));
}

__device__ __forceinline__ void cp16(uint32_t smem, const float* gptr, bool valid) {
    int sz = valid ? 16 : 0;
    asm volatile("cp.async.cg.shared.global [%0], [%1], 16, %2;"
                 :: "r"(smem), "l"(gptr), "r"(sz));
}

template <int MODE, int BN>
__device__ __forceinline__ void gemm_tf32_body(const float* __restrict__ A,
                                               const float* __restrict__ B,
                                               __half* __restrict__ Ch,
                                               int M, int Nn, int K,
                                               const float* __restrict__ av_src,
                                               const float* __restrict__ av_dst) {
    constexpr int TNT = BN / 16;                 // 8-wide n-tiles per warp
    constexpr int GBP = (BN == 128) ? 136 : 72;  // Bs row stride (floats)
    constexpr int NH  = (MODE == 1) ? (BN / 64) : 1;  // heads per warp (alpha partials)
    constexpr int BF4 = BN / 64;                 // B float4 loads per thread

    __shared__ float As[2][128 * GA_PAD];
    __shared__ float Bs[2][16 * GBP];

    int tid = threadIdx.x;
    int wid = tid >> 5, lane = tid & 31;
    int lq = lane >> 2, lr = lane & 3;
    int warp_m = wid & 3, warp_n = wid >> 2;
    int row0 = blockIdx.y * 128, col0 = blockIdx.x * BN;
    int wcol = col0 + warp_n * (BN / 2);

    uint32_t as_base = (uint32_t)__cvta_generic_to_shared(&As[0][0]);
    uint32_t bs_base = (uint32_t)__cvta_generic_to_shared(&Bs[0][0]);
    const uint32_t as_stage = 128 * GA_PAD * 4;
    const uint32_t bs_stage = 16 * GBP * 4;

    float acc[2][TNT][4];
#pragma unroll
    for (int i = 0; i < 2; i++)
#pragma unroll
        for (int j = 0; j < TNT; j++)
#pragma unroll
            for (int q = 0; q < 4; q++) acc[i][j][q] = 0.f;

    int a_row[2], a_col[2];
#pragma unroll
    for (int u = 0; u < 2; u++) {
        int idx = tid + 256 * u;
        a_row[u] = idx >> 2;
        a_col[u] = (idx & 3) * 4;
    }

    int nk = K >> 4;

    auto issue = [&](int kt, int stage) {
#pragma unroll
        for (int u = 0; u < 2; u++) {
            int r = row0 + a_row[u];
            bool v = (r < M);
            const float* gp = A + (long)(v ? r : 0) * K + (kt << 4) + a_col[u];
            cp16(as_base + stage * as_stage + (a_row[u] * GA_PAD + a_col[u]) * 4, gp, v);
        }
#pragma unroll
        for (int u = 0; u < BF4; u++) {
            int idx = tid + 256 * u;
            int br = idx / (BN / 4);
            int bc = (idx % (BN / 4)) * 4;
            const float* gp = B + (long)((kt << 4) + br) * Nn + col0 + bc;
            cp16(bs_base + stage * bs_stage + (br * GBP + bc) * 4, gp, true);
        }
        asm volatile("cp.async.commit_group;");
    };

    issue(0, 0);

    for (int kt = 0; kt < nk; kt++) {
        int stage = kt & 1;
        if (kt + 1 < nk) {
            issue(kt + 1, stage ^ 1);
            asm volatile("cp.async.wait_group 1;");
        } else {
            asm volatile("cp.async.wait_group 0;");
        }
        __syncthreads();

        const float* Asb = &As[stage][0];
        const float* Bsb = &Bs[stage][0];
#pragma unroll
        for (int kk = 0; kk < 16; kk += 8) {
            uint32_t af[2][4], bf[TNT][2];
#pragma unroll
            for (int tm = 0; tm < 2; tm++) {
                int bm = warp_m * 32 + tm * 16;
                const float* ap = Asb + kk + lr;
                af[tm][0] = cvt_tf32(__float_as_uint(ap[(bm + lq) * GA_PAD]));
                af[tm][1] = cvt_tf32(__float_as_uint(ap[(bm + lq + 8) * GA_PAD]));
                af[tm][2] = cvt_tf32(__float_as_uint(ap[(bm + lq) * GA_PAD + 4]));
                af[tm][3] = cvt_tf32(__float_as_uint(ap[(bm + lq + 8) * GA_PAD + 4]));
            }
#pragma unroll
            for (int tn = 0; tn < TNT; tn++) {
                int bb = warp_n * (BN / 2) + tn * 8 + lq;
                bf[tn][0] = __float_as_uint(Bsb[(kk + lr) * GBP + bb]);
                bf[tn][1] = __float_as_uint(Bsb[(kk + lr + 4) * GBP + bb]);
            }
#pragma unroll
            for (int tm = 0; tm < 2; tm++)
#pragma unroll
                for (int tn = 0; tn < TNT; tn++)
                    mma_tf32(acc[tm][tn], af[tm], bf[tn]);
        }
        __syncthreads();
    }

    // ---- store C as fp16 (half2 pairs) ----
#pragma unroll
    for (int tm = 0; tm < 2; tm++) {
        int r0 = row0 + warp_m * 32 + tm * 16 + lq;
#pragma unroll
        for (int tn = 0; tn < TNT; tn++) {
            int c = wcol + tn * 8 + 2 * lr;
            if (r0 < M) {
                __half2* p = (__half2*)(Ch + (long)r0 * Nn + c);
                *p = __floats2half2_rn(acc[tm][tn][0], acc[tm][tn][1]);
            }
            if (r0 + 8 < M) {
                __half2* p = (__half2*)(Ch + (long)(r0 + 8) * Nn + c);
                *p = __floats2half2_rn(acc[tm][tn][2], acc[tm][tn][3]);
            }
        }
    }

    // ---- fused alpha epilogue (fp32 accumulators); NH per-warp heads ----
    float ps[NH][2][2], pd[NH][2][2];
#pragma unroll
    for (int hl = 0; hl < NH; hl++)
#pragma unroll
        for (int tm = 0; tm < 2; tm++)
#pragma unroll
            for (int hf = 0; hf < 2; hf++) { ps[hl][tm][hf] = 0.f; pd[hl][tm][hf] = 0.f; }

#pragma unroll
    for (int tn = 0; tn < TNT; tn++) {
        int hl = (MODE == 1) ? (tn >> 2) % NH : 0;   // local head index
        float s0, s1, d0, d1;
        if (MODE == 1) {
            int head = (wcol >> 5) + (tn >> 2);
            int ch = (tn & 3) * 8 + 2 * lr;
            s0 = av_src[head * C1 + ch];     s1 = av_src[head * C1 + ch + 1];
            d0 = av_dst[head * C1 + ch];     d1 = av_dst[head * C1 + ch + 1];
        } else {
            int c = warp_n * (BN / 2) + tn * 8 + 2 * lr;
            s0 = av_src[c]; s1 = av_src[c + 1];
            d0 = av_dst[c]; d1 = av_dst[c + 1];
        }
#pragma unroll
        for (int tm = 0; tm < 2; tm++) {
            ps[hl][tm][0] = fmaf(s0, acc[tm][tn][0], fmaf(s1, acc[tm][tn][1], ps[hl][tm][0]));
            ps[hl][tm][1] = fmaf(s0, acc[tm][tn][2], fmaf(s1, acc[tm][tn][3], ps[hl][tm][1]));
            pd[hl][tm][0] = fmaf(d0, acc[tm][tn][0], fmaf(d1, acc[tm][tn][1], pd[hl][tm][0]));
            pd[hl][tm][1] = fmaf(d0, acc[tm][tn][2], fmaf(d1, acc[tm][tn][3], pd[hl][tm][1]));
        }
    }
#pragma unroll
    for (int hl = 0; hl < NH; hl++)
#pragma unroll
        for (int tm = 0; tm < 2; tm++)
#pragma unroll
            for (int hf = 0; hf < 2; hf++) {
                ps[hl][tm][hf] += __shfl_xor_sync(0xffffffffu, ps[hl][tm][hf], 1);
                ps[hl][tm][hf] += __shfl_xor_sync(0xffffffffu, ps[hl][tm][hf], 2);
                pd[hl][tm][hf] += __shfl_xor_sync(0xffffffffu, pd[hl][tm][hf], 1);
                pd[hl][tm][hf] += __shfl_xor_sync(0xffffffffu, pd[hl][tm][hf], 2);
            }
    if (lr == 0) {
#pragma unroll
        for (int hl = 0; hl < NH; hl++)
#pragma unroll
            for (int tm = 0; tm < 2; tm++)
#pragma unroll
                for (int hf = 0; hf < 2; hf++) {
                    int r = row0 + warp_m * 32 + tm * 16 + lq + hf * 8;
                    if (r < M) {
                        if (MODE == 1) {
                            int head = (wcol >> 5) + hl;
                            g_as1[r * H1 + head] = ps[hl][tm][hf];
                            g_ad1[r * H1 + head] = pd[hl][tm][hf];
                        } else {
                            atomicAdd(&g_as2[r], ps[hl][tm][hf]);
                            atomicAdd(&g_ad2[r], pd[hl][tm][hf]);
                        }
                    }
                }
    }
}

__global__ void gemm1_k(const float* __restrict__ A, int M,
                        const float* __restrict__ av_src, const float* __restrict__ av_dst) {
    gemm_tf32_body<1, 128>(A, g_w1c, g_xw1h, M, D1, FIN, av_src, av_dst);
}
__global__ void gemm2_k(int M,
                        const float* __restrict__ av_src, const float* __restrict__ av_dst) {
    gemm_tf32_body<2, 64>(g_h, g_w2c, g_h2h, M, OUTC, D1, av_src, av_dst);
}

// ---------------- layer-1 aggregation: one WARP per node, 1x LDG.128 per edge ----
__global__ void agg1_k(const float* __restrict__ b1, int N) {
    int warp = (blockIdx.x * blockDim.x + threadIdx.x) >> 5;
    if (warp >= N) return;
    int n = warp;
    int lane = threadIdx.x & 31;
    int beg = g_off[n], end = g_off[n + 1];
    int src_lane = lane >> 2;

    float ad = (lane < H1) ? g_ad1[n * H1 + lane] : 0.f;

    float denom = 0.f;
    float acc[8];
#pragma unroll
    for (int j = 0; j < 8; j++) acc[j] = 0.f;

    int k = beg;
    for (; k + 1 < end; k += 2) {
        int s0 = g_csr[k], s1 = g_csr[k + 1];
        float as0 = (lane < H1) ? g_as1[s0 * H1 + lane] : 0.f;
        float as1v = (lane < H1) ? g_as1[s1 * H1 + lane] : 0.f;
        uint4 p0 = *(const uint4*)(g_xw1h + (long)s0 * D1 + lane * 8);
        uint4 p1 = *(const uint4*)(g_xw1h + (long)s1 * D1 + lane * 8);
        float e0 = as0 + ad; e0 = (e0 > 0.f) ? e0 : 0.2f * e0;
        float e1 = as1v + ad; e1 = (e1 > 0.f) ? e1 : 0.2f * e1;
        float w0 = __expf(e0), w1 = __expf(e1);
        denom += w0;
        float wh0 = __shfl_sync(0xffffffffu, w0, src_lane);
        {
            uint32_t us[4] = {p0.x, p0.y, p0.z, p0.w};
#pragma unroll
            for (int q = 0; q < 4; q++) {
                float2 f = __half22float2(*(__half2*)&us[q]);
                acc[2 * q]     = fmaf(wh0, f.x, acc[2 * q]);
                acc[2 * q + 1] = fmaf(wh0, f.y, acc[2 * q + 1]);
            }
        }
        denom += w1;
        float wh1 = __shfl_sync(0xffffffffu, w1, src_lane);
        {
            uint32_t us[4] = {p1.x, p1.y, p1.z, p1.w};
#pragma unroll
            for (int q = 0; q < 4; q++) {
                float2 f = __half22float2(*(__half2*)&us[q]);
                acc[2 * q]     = fmaf(wh1, f.x, acc[2 * q]);
                acc[2 * q + 1] = fmaf(wh1, f.y, acc[2 * q + 1]);
            }
        }
    }
    if (k < end) {
        int s = g_csr[k];
        float as = (lane < H1) ? g_as1[s * H1 + lane] : 0.f;
        float e = as + ad;
        e = (e > 0.f) ? e : 0.2f * e;
        float w = __expf(e);
        denom += w;
        float wh = __shfl_sync(0xffffffffu, w, src_lane);
        uint4 pkt = *(const uint4*)(g_xw1h + (long)s * D1 + lane * 8);
        uint32_t us[4] = {pkt.x, pkt.y, pkt.z, pkt.w};
#pragma unroll
        for (int q = 0; q < 4; q++) {
            float2 f = __half22float2(*(__half2*)&us[q]);
            acc[2 * q]     = fmaf(wh, f.x, acc[2 * q]);
            acc[2 * q + 1] = fmaf(wh, f.y, acc[2 * q + 1]);
        }
    }
    float inv = 1.f / (denom + 1e-16f);
    float invh = __shfl_sync(0xffffffffu, inv, src_lane);

    float o[8];
#pragma unroll
    for (int j = 0; j < 8; j++) {
        float v = acc[j] * invh + b1[lane * 8 + j];
        o[j] = (v > 0.f) ? v : (__expf(v) - 1.f);
    }
    float4* dst = (float4*)(g_h + (long)n * D1 + lane * 8);
    dst[0] = make_float4(o[0], o[1], o[2], o[3]);
    dst[1] = make_float4(o[4], o[5], o[6], o[7]);
}

// ---------------- layer-2 aggregation + bias + log_softmax ----------------
__global__ void agg2_k(const float* __restrict__ b2, float* __restrict__ out, int N) {
    int warp = (blockIdx.x * blockDim.x + threadIdx.x) >> 5;
    if (warp >= N) return;
    int n = warp;
    int lane = threadIdx.x & 31;
    int beg = g_off[n], end = g_off[n + 1];
    float ad = g_ad2[n];

    float denom = 0.f, a0 = 0.f, a1 = 0.f;
    int k = beg;
    for (; k + 1 < end; k += 2) {
        int s0 = g_csr[k], s1 = g_csr[k + 1];
        float e0 = g_as2[s0] + ad; e0 = (e0 > 0.f) ? e0 : 0.2f * e0;
        float e1 = g_as2[s1] + ad; e1 = (e1 > 0.f) ? e1 : 0.2f * e1;
        __half2 h0 = *(const __half2*)(g_h2h + (long)s0 * OUTC + lane * 2);
        __half2 h1 = *(const __half2*)(g_h2h + (long)s1 * OUTC + lane * 2);
        float w0 = __expf(e0), w1 = __expf(e1);
        float2 f0 = __half22float2(h0), f1 = __half22float2(h1);
        denom += w0;
        a0 = fmaf(w0, f0.x, a0);
        a1 = fmaf(w0, f0.y, a1);
        denom += w1;
        a0 = fmaf(w1, f1.x, a0);
        a1 = fmaf(w1, f1.y, a1);
    }
    if (k < end) {
        int s = g_csr[k];
        float e = g_as2[s] + ad;
        e = (e > 0.f) ? e : 0.2f * e;
        float w = __expf(e);
        denom += w;
        __half2 hv = *(const __half2*)(g_h2h + (long)s * OUTC + lane * 2);
        float2 f = __half22float2(hv);
        a0 = fmaf(w, f.x, a0);
        a1 = fmaf(w, f.y, a1);
    }
    float inv = 1.f / (denom + 1e-16f);
    a0 = a0 * inv + b2[lane * 2];
    a1 = a1 * inv + b2[lane * 2 + 1];

    float mx = fmaxf(a0, a1);
#pragma unroll
    for (int o = 16; o; o >>= 1) mx = fmaxf(mx, __shfl_xor_sync(0xffffffffu, mx, o));
    float sum = __expf(a0 - mx) + __expf(a1 - mx);
#pragma unroll
    for (int o = 16; o; o >>= 1) sum += __shfl_xor_sync(0xffffffffu, sum, o);
    float lse = mx + __logf(sum);
    float2* po = (float2*)(out + (long)n * OUTC + lane * 2);
    *po = make_float2(a0 - lse, a1 - lse);
}

// ---------------- launch ----------------
extern "C" void kernel_launch(void* const* d_in, const int* in_sizes, int n_in,
                              void* d_out, int out_size) {
    const float* x   = (const float*)d_in[0];
    const void*  ei  = d_in[1];
    const float* W1  = (const float*)d_in[2];
    const float* as1 = (const float*)d_in[3];
    const float* ad1 = (const float*)d_in[4];
    const float* b1  = (const float*)d_in[5];
    const float* W2  = (const float*)d_in[6];
    const float* as2 = (const float*)d_in[7];
    const float* ad2 = (const float*)d_in[8];
    const float* b2  = (const float*)d_in[9];
    float* out = (float*)d_out;

    int E = in_sizes[1] / 2;
    int N = in_sizes[0] / FIN;
    int ET = E + N;
    int nb = (N + 1023) / 1024;

    cudaStream_t s2;
    cudaStreamCreateWithFlags(&s2, cudaStreamNonBlocking);
    cudaEvent_t eFork, eJoin;
    cudaEventCreateWithFlags(&eFork, cudaEventDisableTiming);
    cudaEventCreateWithFlags(&eJoin, cudaEventDisableTiming);

    cudaEventRecord(eFork, 0);
    cudaStreamWaitEvent(s2, eFork, 0);

    // Submission order puts gemm1 4th (the launch ncu's -s 5 -c 1 samples).
    wconv_k<<<160, 256>>>(W1, W2);                                   // #1 (default)
    detect_k<<<1, 64, 0, s2>>>((const unsigned*)ei);                 // #2 (s2)
    zero_deg_k<<<(N + 255) / 256, 256, 0, s2>>>(N);                  // #3 (s2)
    {
        dim3 grid(D1 / 128, (N + 127) / 128);
        gemm1_k<<<grid, 256>>>(x, N, as1, ad1);                      // #4 (default)
    }
    count_deg_k<<<(ET + 255) / 256, 256, 0, s2>>>(ei, E, N);         // #5 (s2)
    scanA_k<<<nb, 1024, 0, s2>>>(N);                                 // #6
    scanB_k<<<1, 64, 0, s2>>>(nb, N);
    scanC_k<<<nb, 1024, 0, s2>>>(N);
    fill_csr_k<<<(ET + 255) / 256, 256, 0, s2>>>(ei, E, N);
    cudaEventRecord(eJoin, s2);

    cudaStreamWaitEvent(0, eJoin, 0);

    agg1_k<<<(N * 32 + 255) / 256, 256>>>(b1, N);
    {
        dim3 grid(OUTC / 64, (N + 127) / 128);
        gemm2_k<<<grid, 256>>>(N, as2, ad2);
    }
    agg2_k<<<(N * 32 + 255) / 256, 256>>>(b2, out, N);

    cudaEventDestroy(eFork);
    cudaEventDestroy(eJoin);
    cudaStreamDestroy(s2);
}